// round 1
// baseline (speedup 1.0000x reference)
#include <cuda_runtime.h>
#include <math.h>

// ---------------- problem constants ----------------
#define PPB   2256          // pairs per batch (48*47)
#define MROWS 36096         // BSZ * PPB
#define NDET  48
#define NB    92            // base classes
#define NLAB  133           // 1 + 92 + 40

// ---------------- scratch (__device__ globals; no allocations) ----------------
__device__ float g_UV[768 * 2048];                    // [768, 2048]: cols 0..1023 = U, 1024..2047 = V
__device__ float g_h2[(size_t)MROWS * 1024];          // 147.8 MB
__device__ float g_sp[(size_t)MROWS * 512];           // so_proj, 74 MB
__device__ float g_rh[(size_t)MROWS * 256];           // relu(rp@R1+rb1), 37 MB
__device__ float g_re[(size_t)MROWS * 512];           // rh@R2, 74 MB
__device__ double g_acc[3];                           // pos_sum, neg_sum, distil_sum
__device__ unsigned int g_cnt[2];                     // pos_count, neg_count

// ---------------- init: zero accumulators (runs inside the graph every replay) ----------------
__global__ void init_acc_kernel() {
    g_acc[0] = 0.0; g_acc[1] = 0.0; g_acc[2] = 0.0;
    g_cnt[0] = 0u;  g_cnt[1] = 0u;
}

// ---------------- generic 128x128x16 SGEMM (M,N mult of 128, K mult of 16) ----------------
__global__ void __launch_bounds__(256)
sgemm_plain(int M, int N, int K,
            const float* __restrict__ A, int lda,
            const float* __restrict__ B, int ldb,
            float* __restrict__ C, int ldc)
{
    __shared__ float As[16][132];
    __shared__ float Bs[16][132];
    const int tid = threadIdx.x;
    const int tx = tid & 15;
    const int ty = tid >> 4;
    const int rowBlk = blockIdx.y * 128;
    const int colBlk = blockIdx.x * 128;

    float acc[8][8];
#pragma unroll
    for (int i = 0; i < 8; i++)
#pragma unroll
        for (int j = 0; j < 8; j++) acc[i][j] = 0.f;

    for (int k0 = 0; k0 < K; k0 += 16) {
#pragma unroll
        for (int j = 0; j < 2; j++) {
            int lin = tid + j * 256;           // 0..511
            int m   = lin >> 2;                // 0..127
            int kq  = (lin & 3) << 2;          // 0,4,8,12
            float4 av = *reinterpret_cast<const float4*>(
                A + (size_t)(rowBlk + m) * lda + k0 + kq);
            As[kq + 0][m] = av.x; As[kq + 1][m] = av.y;
            As[kq + 2][m] = av.z; As[kq + 3][m] = av.w;
        }
#pragma unroll
        for (int j = 0; j < 2; j++) {
            int lin = tid + j * 256;
            int kk  = lin >> 5;                // 0..15
            int nq  = (lin & 31) << 2;         // 0..124
            *reinterpret_cast<float4*>(&Bs[kk][nq]) =
                *reinterpret_cast<const float4*>(
                    B + (size_t)(k0 + kk) * ldb + colBlk + nq);
        }
        __syncthreads();
#pragma unroll
        for (int kk = 0; kk < 16; kk++) {
            float4 a0 = *reinterpret_cast<const float4*>(&As[kk][ty * 8]);
            float4 a1 = *reinterpret_cast<const float4*>(&As[kk][ty * 8 + 4]);
            float4 b0 = *reinterpret_cast<const float4*>(&Bs[kk][tx * 8]);
            float4 b1v = *reinterpret_cast<const float4*>(&Bs[kk][tx * 8 + 4]);
            float a[8] = {a0.x, a0.y, a0.z, a0.w, a1.x, a1.y, a1.z, a1.w};
            float b[8] = {b0.x, b0.y, b0.z, b0.w, b1v.x, b1v.y, b1v.z, b1v.w};
#pragma unroll
            for (int i = 0; i < 8; i++)
#pragma unroll
                for (int jj = 0; jj < 8; jj++)
                    acc[i][jj] = fmaf(a[i], b[jj], acc[i][jj]);
        }
        __syncthreads();
    }
#pragma unroll
    for (int i = 0; i < 8; i++) {
        int row = rowBlk + ty * 8 + i;
        float4 c0 = make_float4(acc[i][0], acc[i][1], acc[i][2], acc[i][3]);
        float4 c1 = make_float4(acc[i][4], acc[i][5], acc[i][6], acc[i][7]);
        *reinterpret_cast<float4*>(C + (size_t)row * ldc + colBlk + tx * 8)     = c0;
        *reinterpret_cast<float4*>(C + (size_t)row * ldc + colBlk + tx * 8 + 4) = c1;
    }
}

// ---------------- GEMM2: A computed on the fly = relu(U[s]+V[o]+b1); epilogue relu(+b2) ----------------
__global__ void __launch_bounds__(256)
sgemm_pair(const float* __restrict__ b1,
           const float* __restrict__ W2,
           const float* __restrict__ b2,
           const int* __restrict__ sids,
           const int* __restrict__ oids)
{
    __shared__ float As[16][132];
    __shared__ float Bs[16][132];
    __shared__ int urow[128], vrow[128];
    const int tid = threadIdx.x;
    const int tx = tid & 15;
    const int ty = tid >> 4;
    const int rowBlk = blockIdx.y * 128;
    const int colBlk = blockIdx.x * 128;

    if (tid < 128) {
        int r = rowBlk + tid;
        int b = r / PPB;
        int p = r - b * PPB;
        urow[tid] = b * NDET + sids[p];
        vrow[tid] = b * NDET + oids[p];
    }
    __syncthreads();

    float acc[8][8];
#pragma unroll
    for (int i = 0; i < 8; i++)
#pragma unroll
        for (int j = 0; j < 8; j++) acc[i][j] = 0.f;

    for (int k0 = 0; k0 < 1024; k0 += 16) {
        // fused A: h1[m][k] = relu(U[urow[m]][k] + V[vrow[m]][k] + b1[k])
#pragma unroll
        for (int j = 0; j < 8; j++) {
            int lin = tid + j * 256;           // 0..2047
            int m   = lin >> 4;                // 0..127
            int kk  = lin & 15;                // 0..15 (contiguous per-thread-group => coalesced)
            float u = g_UV[(size_t)urow[m] * 2048 + k0 + kk];
            float v = g_UV[(size_t)vrow[m] * 2048 + 1024 + k0 + kk];
            As[kk][m] = fmaxf(u + v + __ldg(b1 + k0 + kk), 0.f);
        }
#pragma unroll
        for (int j = 0; j < 2; j++) {
            int lin = tid + j * 256;
            int kk  = lin >> 5;
            int nq  = (lin & 31) << 2;
            *reinterpret_cast<float4*>(&Bs[kk][nq]) =
                *reinterpret_cast<const float4*>(
                    W2 + (size_t)(k0 + kk) * 1024 + colBlk + nq);
        }
        __syncthreads();
#pragma unroll
        for (int kk = 0; kk < 16; kk++) {
            float4 a0 = *reinterpret_cast<const float4*>(&As[kk][ty * 8]);
            float4 a1 = *reinterpret_cast<const float4*>(&As[kk][ty * 8 + 4]);
            float4 b0 = *reinterpret_cast<const float4*>(&Bs[kk][tx * 8]);
            float4 b1v = *reinterpret_cast<const float4*>(&Bs[kk][tx * 8 + 4]);
            float a[8] = {a0.x, a0.y, a0.z, a0.w, a1.x, a1.y, a1.z, a1.w};
            float b[8] = {b0.x, b0.y, b0.z, b0.w, b1v.x, b1v.y, b1v.z, b1v.w};
#pragma unroll
            for (int i = 0; i < 8; i++)
#pragma unroll
                for (int jj = 0; jj < 8; jj++)
                    acc[i][jj] = fmaf(a[i], b[jj], acc[i][jj]);
        }
        __syncthreads();
    }
    // epilogue: relu(acc + b2)
    float bb[8];
#pragma unroll
    for (int jj = 0; jj < 8; jj++) bb[jj] = __ldg(b2 + colBlk + tx * 8 + jj);
#pragma unroll
    for (int i = 0; i < 8; i++) {
        int row = rowBlk + ty * 8 + i;
        float4 c0, c1;
        c0.x = fmaxf(acc[i][0] + bb[0], 0.f);
        c0.y = fmaxf(acc[i][1] + bb[1], 0.f);
        c0.z = fmaxf(acc[i][2] + bb[2], 0.f);
        c0.w = fmaxf(acc[i][3] + bb[3], 0.f);
        c1.x = fmaxf(acc[i][4] + bb[4], 0.f);
        c1.y = fmaxf(acc[i][5] + bb[5], 0.f);
        c1.z = fmaxf(acc[i][6] + bb[6], 0.f);
        c1.w = fmaxf(acc[i][7] + bb[7], 0.f);
        *reinterpret_cast<float4*>(g_h2 + (size_t)row * 1024 + colBlk + tx * 8)     = c0;
        *reinterpret_cast<float4*>(g_h2 + (size_t)row * 1024 + colBlk + tx * 8 + 4) = c1;
    }
}

// ---------------- relpos hidden: rh = relu(rp @ R1 + rb1), K=12 ----------------
__global__ void __launch_bounds__(256)
rh_kernel(const float* __restrict__ rp,
          const float* __restrict__ R1,
          const float* __restrict__ rb1)
{
    const int r = blockIdx.x;
    const int c = threadIdx.x;
    __shared__ float x[12];
    if (c < 12) x[c] = rp[(size_t)r * 12 + c];
    __syncthreads();
    float acc = __ldg(rb1 + c);
#pragma unroll
    for (int t = 0; t < 12; t++) acc = fmaf(x[t], __ldg(R1 + t * 256 + c), acc);
    g_rh[(size_t)r * 256 + c] = fmaxf(acc, 0.f);
}

// ---------------- epilogue helpers ----------------
__device__ __forceinline__ float blockReduce128(float v, volatile float* red) {
#pragma unroll
    for (int o = 16; o > 0; o >>= 1) v += __shfl_down_sync(0xffffffffu, v, o);
    __syncthreads();   // protect red[] from previous use
    if ((threadIdx.x & 31) == 0) red[threadIdx.x >> 5] = v;
    __syncthreads();
    return red[0] + red[1] + red[2] + red[3];
}

__device__ __forceinline__ float focal_loss(float x, float t) {
    float p  = 1.0f / (1.0f + expf(-x));
    float ce = fmaxf(x, 0.0f) - x * t + log1pf(expf(-fabsf(x)));
    float pt = p * t + (1.0f - p) * (1.0f - t);
    float om = 1.0f - pt;
    float at = 0.25f * t + 0.75f * (1.0f - t);
    return at * ce * om * om;
}

// ---------------- per-row epilogue: norms, logits, focal, distil ----------------
__global__ void __launch_bounds__(128)
epilogue_kernel(const float* __restrict__ cw,
                const float* __restrict__ temp,
                const int* __restrict__ labels,
                const int* __restrict__ sids,
                const int* __restrict__ oids,
                const float* __restrict__ traj)
{
    const int r   = blockIdx.x;
    const int tid = threadIdx.x;
    __shared__ float sp[512];
    __shared__ float comb[512];
    __shared__ float red[4];
    __shared__ int   labsh[93];
    __shared__ int   s_pos;

    const int b = r / PPB;
    const int p = r - b * PPB;

    float ssp = 0.f, sre = 0.f;
    for (int k = tid; k < 512; k += 128) {
        float a = g_sp[(size_t)r * 512 + k];
        float e = g_re[(size_t)r * 512 + k];
        sp[k] = a; comb[k] = e;
        ssp += a * a; sre += e * e;
    }
    if (tid < 93) labsh[tid] = labels[(size_t)r * NLAB + tid];
    if (tid == 0) s_pos = 0;

    float tssp = blockReduce128(ssp, red);
    float tsre = blockReduce128(sre, red);
    float inv_sp = 1.f / fmaxf(sqrtf(tssp), 1e-12f);
    float inv_re = 1.f / fmaxf(sqrtf(tsre), 1e-12f);

    float ssc = 0.f;
    for (int k = tid; k < 512; k += 128) {
        float c = sp[k] * inv_sp + comb[k] * inv_re;
        comb[k] = c;
        ssc += c * c;
    }
    float tssc = blockReduce128(ssc, red);
    float inv_c = 1.f / fmaxf(sqrtf(tssc), 1e-12f);
    for (int k = tid; k < 512; k += 128) comb[k] *= inv_c;
    if (tid < NB && labsh[1 + tid] > 0) s_pos = 1;
    __syncthreads();

    const bool pos = (s_pos != 0);
    const bool neg = (labsh[0] > 0);
    const float inv_t = 1.0f / temp[0];

    float flp = 0.f, fln = 0.f;
    if (tid < NB) {
        const float4* w4 = reinterpret_cast<const float4*>(cw + (size_t)tid * 512);
        const float4* c4 = reinterpret_cast<const float4*>(comb);
        float x = 0.f;
#pragma unroll 4
        for (int k = 0; k < 128; k++) {
            float4 w = w4[k]; float4 c = c4[k];
            x += w.x * c.x + w.y * c.y + w.z * c.z + w.w * c.w;
        }
        x *= inv_t;
        float t = (float)labsh[1 + tid];
        flp = focal_loss(x, t);
        fln = focal_loss(x, 0.f);
    }

    // distil: |concat(traj[s], traj[o]) - so_proj| (so_proj raw, in sp[])
    const float* ts = traj + ((size_t)b * NDET + sids[p]) * 256;
    const float* to = traj + ((size_t)b * NDET + oids[p]) * 256;
    float d = 0.f;
    for (int k = tid; k < 256; k += 128) d += fabsf(ts[k] - sp[k]);
    for (int k = tid; k < 256; k += 128) d += fabsf(to[k] - sp[256 + k]);

    float tpos = blockReduce128(pos ? flp : 0.f, red);
    float tneg = blockReduce128(neg ? fln : 0.f, red);
    float td   = blockReduce128(d, red);

    if (tid == 0) {
        atomicAdd(&g_acc[0], (double)tpos);
        atomicAdd(&g_acc[1], (double)tneg);
        atomicAdd(&g_acc[2], (double)td);
        if (pos) atomicAdd(&g_cnt[0], 1u);
        if (neg) atomicAdd(&g_cnt[1], 1u);
    }
}

// ---------------- finalize ----------------
__global__ void finalize_kernel(float* __restrict__ out) {
    double pc = (double)(g_cnt[0] > 0u ? g_cnt[0] : 1u);
    double nc = (double)(g_cnt[1] > 0u ? g_cnt[1] : 1u);
    double total = g_acc[0] / (pc * (double)NB)
                 + g_acc[1] / (nc * (double)NB)
                 + g_acc[2] / ((double)MROWS * 512.0);
    out[0] = (float)total;
}

// ---------------- launch ----------------
extern "C" void kernel_launch(void* const* d_in, const int* in_sizes, int n_in,
                              void* d_out, int out_size)
{
    const float* det    = (const float*)d_in[0];
    const float* traj   = (const float*)d_in[1];
    const float* rp     = (const float*)d_in[2];
    const float* cw     = (const float*)d_in[3];
    const float* W1     = (const float*)d_in[4];
    const float* b1     = (const float*)d_in[5];
    const float* W2     = (const float*)d_in[6];
    const float* b2     = (const float*)d_in[7];
    const float* W3     = (const float*)d_in[8];
    const float* R1     = (const float*)d_in[9];
    const float* rb1    = (const float*)d_in[10];
    const float* R2     = (const float*)d_in[11];
    const float* temp   = (const float*)d_in[12];
    const int*   labels = (const int*)d_in[13];
    const int*   sids   = (const int*)d_in[14];
    const int*   oids   = (const int*)d_in[15];
    float* out = (float*)d_out;

    void *p_uv, *p_h2, *p_sp, *p_rh, *p_re;
    cudaGetSymbolAddress(&p_uv, g_UV);
    cudaGetSymbolAddress(&p_h2, g_h2);
    cudaGetSymbolAddress(&p_sp, g_sp);
    cudaGetSymbolAddress(&p_rh, g_rh);
    cudaGetSymbolAddress(&p_re, g_re);
    float* UV = (float*)p_uv;
    float* H2 = (float*)p_h2;
    float* SP = (float*)p_sp;
    float* RH = (float*)p_rh;
    float* RE = (float*)p_re;

    init_acc_kernel<<<1, 1>>>();

    // U = det_flat[768,2048] @ W1[:2048]   -> UV cols 0..1023
    sgemm_plain<<<dim3(1024 / 128, 768 / 128), 256>>>(
        768, 1024, 2048, det, 2048, W1, 1024, UV, 2048);
    // V = det_flat @ W1[2048:]             -> UV cols 1024..2047
    sgemm_plain<<<dim3(1024 / 128, 768 / 128), 256>>>(
        768, 1024, 2048, det, 2048, W1 + (size_t)2048 * 1024, 1024, UV + 1024, 2048);

    // h2 = relu(relu(U_s + V_o + b1) @ W2 + b2)
    sgemm_pair<<<dim3(1024 / 128, MROWS / 128), 256>>>(b1, W2, b2, sids, oids);

    // so_proj = h2 @ W3
    sgemm_plain<<<dim3(512 / 128, MROWS / 128), 256>>>(
        MROWS, 512, 1024, H2, 1024, W3, 512, SP, 512);

    // rh = relu(rp @ R1 + rb1)
    rh_kernel<<<MROWS, 256>>>(rp, R1, rb1);

    // re_raw = rh @ R2
    sgemm_plain<<<dim3(512 / 128, MROWS / 128), 256>>>(
        MROWS, 512, 256, RH, 256, R2, 512, RE, 512);

    // norms + logits + focal + distil, accumulated in doubles
    epilogue_kernel<<<MROWS, 128>>>(cw, temp, labels, sids, oids, traj);

    finalize_kernel<<<1, 1>>>(out);
}

// round 3
// speedup vs baseline: 2.8856x; 2.8856x over previous
#include <cuda_runtime.h>
#include <math.h>
#include <cstdint>

// ---------------- problem constants ----------------
#define PPB   2256          // pairs per batch (48*47)
#define MROWS 36096         // BSZ * PPB
#define NDET  48
#define NB    92            // base classes
#define NLAB  133           // 1 + 92 + 40

// ---------------- scratch (__device__ globals; no allocations) ----------------
__device__ float g_UV[768 * 2048];                    // [768,2048]: cols 0..1023 = U, 1024..2047 = V
__device__ float g_h2[(size_t)MROWS * 1024];
__device__ float g_sp[(size_t)MROWS * 512];
__device__ float g_rh[(size_t)MROWS * 256];
__device__ float g_re[(size_t)MROWS * 512];
__device__ float g_W1tU[1024 * 2048];                 // W1[0:2048,:]^T   [N=1024][K=2048]
__device__ float g_W1tV[1024 * 2048];                 // W1[2048:,:]^T
__device__ float g_W2t[1024 * 1024];                  // W2^T [1024][1024]
__device__ float g_W3t[512 * 1024];                   // W3^T [512][1024]
__device__ float g_R2t[512 * 256];                    // R2^T [512][256]
__device__ double g_acc[3];
__device__ unsigned int g_cnt[2];

// ---------------- tf32 helpers ----------------
__device__ __forceinline__ float to_tf32(float x) {
    uint32_t u;
    asm("cvt.rna.tf32.f32 %0, %1;" : "=r"(u) : "f"(x));
    return __uint_as_float(u);
}
__device__ __forceinline__ void mma1688(float* d,
                                        uint32_t a0, uint32_t a1, uint32_t a2, uint32_t a3,
                                        uint32_t b0, uint32_t b1) {
    asm volatile(
        "mma.sync.aligned.m16n8k8.row.col.f32.tf32.tf32.f32 "
        "{%0,%1,%2,%3}, {%4,%5,%6,%7}, {%8,%9}, {%0,%1,%2,%3};"
        : "+f"(d[0]), "+f"(d[1]), "+f"(d[2]), "+f"(d[3])
        : "r"(a0), "r"(a1), "r"(a2), "r"(a3), "r"(b0), "r"(b1));
}

// ---------------- init ----------------
__global__ void init_acc_kernel() {
    g_acc[0] = 0.0; g_acc[1] = 0.0; g_acc[2] = 0.0;
    g_cnt[0] = 0u;  g_cnt[1] = 0u;
}

// ---------------- weight transpose: dst[n][k] = src[k][n] ----------------
__global__ void __launch_bounds__(256)
transpose_kernel(const float* __restrict__ src, float* __restrict__ dst, int K, int N)
{
    __shared__ float t[32][33];
    int kb = blockIdx.y * 32, nb = blockIdx.x * 32;
    int x = threadIdx.x, y = threadIdx.y;
#pragma unroll
    for (int i = y; i < 32; i += 8) t[i][x] = src[(size_t)(kb + i) * N + nb + x];
    __syncthreads();
#pragma unroll
    for (int i = y; i < 32; i += 8) dst[(size_t)(nb + i) * K + kb + x] = t[x][i];
}

// =====================================================================
// tf32 mma.sync GEMM: C[128x128 tile] = A[M,K] (row-major) x Bt[N,K]^T
// MODE 0: A from global, passthrough epilogue.
// MODE 1: A = relu(U[urow]+V[vrow]+b1) fused from g_UV; epilogue relu(x+b2).
// Smem: double-buffered A/B tiles, pad-36 rows (bank-conflict-free frags).
// =====================================================================
#define APAD 36
#define TILE_BYTES (128 * APAD * 4)      // 18432

template<int MODE>
__global__ void __launch_bounds__(256, 1)
mma_gemm(int K,
         const float* __restrict__ A, int lda,
         const float* __restrict__ Bt,
         float* __restrict__ C, int ldc,
         const float* __restrict__ b1, const float* __restrict__ b2,
         const int* __restrict__ sids, const int* __restrict__ oids)
{
    extern __shared__ char smem[];
    __shared__ int urow[128], vrow[128];

    const int tid  = threadIdx.x;
    const int wid  = tid >> 5;
    const int lane = tid & 31;
    const int rowBlk = blockIdx.y * 128;
    const int colBlk = blockIdx.x * 128;

    const int wm = (wid & 1) * 64;      // warp row offset within tile
    const int wn = (wid >> 1) * 32;     // warp col offset
    const int g  = lane >> 2;           // group id 0..7
    const int tg = lane & 3;            // thread-in-group 0..3

    if (MODE == 1 && tid < 128) {
        int r = rowBlk + tid;
        int b = r / PPB, p = r - b * PPB;
        urow[tid] = b * NDET + sids[p];
        vrow[tid] = b * NDET + oids[p];
    }
    if (MODE == 1) __syncthreads();

    float* AsBase = reinterpret_cast<float*>(smem);                  // 2 stages
    float* BsBase = reinterpret_cast<float*>(smem + 2 * TILE_BYTES); // 2 stages

    float acc[4][4][4];
#pragma unroll
    for (int i = 0; i < 4; i++)
#pragma unroll
        for (int j = 0; j < 4; j++)
#pragma unroll
            for (int q = 0; q < 4; q++) acc[i][j][q] = 0.f;

    float4 ra[4], rav[4], rb[4];

    // per-thread load coordinates (row, float4-slot)
    int amr[4], aq[4];
#pragma unroll
    for (int j = 0; j < 4; ++j) {
        int idx = tid + j * 256;      // 0..1023 over 128x8 float4s
        amr[j] = idx >> 3;
        aq[j]  = idx & 7;
    }

    auto loadChunk = [&](int c) {
        const int k0 = c * 32;
#pragma unroll
        for (int j = 0; j < 4; ++j) {
            const int m = amr[j], q = aq[j];
            if (MODE == 1) {
                ra[j]  = *reinterpret_cast<const float4*>(&g_UV[(size_t)urow[m] * 2048 + k0 + q * 4]);
                rav[j] = *reinterpret_cast<const float4*>(&g_UV[(size_t)vrow[m] * 2048 + 1024 + k0 + q * 4]);
            } else {
                ra[j] = *reinterpret_cast<const float4*>(A + (size_t)(rowBlk + m) * lda + k0 + q * 4);
            }
            rb[j] = *reinterpret_cast<const float4*>(Bt + (size_t)(colBlk + m) * K + k0 + q * 4);
        }
    };
    auto storeChunk = [&](int s, int c) {
        float* As = AsBase + s * (TILE_BYTES / 4);
        float* Bs = BsBase + s * (TILE_BYTES / 4);
        const int k0 = c * 32;
#pragma unroll
        for (int j = 0; j < 4; ++j) {
            const int m = amr[j], q = aq[j];
            float4 av = ra[j];
            if (MODE == 1) {
                const float4 vv = rav[j];
                const float4 bb = *reinterpret_cast<const float4*>(b1 + k0 + q * 4);
                av.x = fmaxf(av.x + vv.x + bb.x, 0.f);
                av.y = fmaxf(av.y + vv.y + bb.y, 0.f);
                av.z = fmaxf(av.z + vv.z + bb.z, 0.f);
                av.w = fmaxf(av.w + vv.w + bb.w, 0.f);
            }
            av.x = to_tf32(av.x); av.y = to_tf32(av.y);
            av.z = to_tf32(av.z); av.w = to_tf32(av.w);
            *reinterpret_cast<float4*>(&As[m * APAD + q * 4]) = av;
            float4 bv = rb[j];
            bv.x = to_tf32(bv.x); bv.y = to_tf32(bv.y);
            bv.z = to_tf32(bv.z); bv.w = to_tf32(bv.w);
            *reinterpret_cast<float4*>(&Bs[m * APAD + q * 4]) = bv;
        }
    };
    auto compute = [&](int s) {
        const float* As = AsBase + s * (TILE_BYTES / 4);
        const float* Bs = BsBase + s * (TILE_BYTES / 4);
#pragma unroll
        for (int ks = 0; ks < 4; ++ks) {
            const int k = ks * 8;
            uint32_t a[4][4], b[4][2];
#pragma unroll
            for (int mt = 0; mt < 4; ++mt) {
                const int r0 = wm + mt * 16;
                a[mt][0] = __float_as_uint(As[(r0 + g)     * APAD + k + tg]);
                a[mt][1] = __float_as_uint(As[(r0 + g + 8) * APAD + k + tg]);
                a[mt][2] = __float_as_uint(As[(r0 + g)     * APAD + k + tg + 4]);
                a[mt][3] = __float_as_uint(As[(r0 + g + 8) * APAD + k + tg + 4]);
            }
#pragma unroll
            for (int nt = 0; nt < 4; ++nt) {
                const int n0 = wn + nt * 8;
                b[nt][0] = __float_as_uint(Bs[(n0 + g) * APAD + k + tg]);
                b[nt][1] = __float_as_uint(Bs[(n0 + g) * APAD + k + tg + 4]);
            }
#pragma unroll
            for (int mt = 0; mt < 4; ++mt)
#pragma unroll
                for (int nt = 0; nt < 4; ++nt)
                    mma1688(acc[mt][nt], a[mt][0], a[mt][1], a[mt][2], a[mt][3],
                            b[nt][0], b[nt][1]);
        }
    };

    const int nch = K >> 5;
    loadChunk(0);
    storeChunk(0, 0);
    __syncthreads();
    int cur = 0;
    for (int c = 0; c < nch; ++c) {
        if (c + 1 < nch) loadChunk(c + 1);
        compute(cur);
        if (c + 1 < nch) storeChunk(cur ^ 1, c + 1);
        __syncthreads();
        cur ^= 1;
    }

    // ---- epilogue: direct float2 stores per fragment ----
#pragma unroll
    for (int mt = 0; mt < 4; ++mt) {
#pragma unroll
        for (int nt = 0; nt < 4; ++nt) {
            const int col = colBlk + wn + nt * 8 + 2 * tg;
            float2 v0 = make_float2(acc[mt][nt][0], acc[mt][nt][1]);
            float2 v1 = make_float2(acc[mt][nt][2], acc[mt][nt][3]);
            if (MODE == 1) {
                const float2 bb = *reinterpret_cast<const float2*>(b2 + col);
                v0.x = fmaxf(v0.x + bb.x, 0.f); v0.y = fmaxf(v0.y + bb.y, 0.f);
                v1.x = fmaxf(v1.x + bb.x, 0.f); v1.y = fmaxf(v1.y + bb.y, 0.f);
            }
            const int row0 = rowBlk + wm + mt * 16 + g;
            *reinterpret_cast<float2*>(C + (size_t)row0 * ldc + col)       = v0;
            *reinterpret_cast<float2*>(C + (size_t)(row0 + 8) * ldc + col) = v1;
        }
    }
}

// ---------------- relpos hidden: rh = relu(rp @ R1 + rb1), K=12 ----------------
__global__ void __launch_bounds__(256)
rh_kernel(const float* __restrict__ rp,
          const float* __restrict__ R1,
          const float* __restrict__ rb1)
{
    const int r = blockIdx.x;
    const int c = threadIdx.x;
    __shared__ float x[12];
    if (c < 12) x[c] = rp[(size_t)r * 12 + c];
    __syncthreads();
    float acc = __ldg(rb1 + c);
#pragma unroll
    for (int t = 0; t < 12; t++) acc = fmaf(x[t], __ldg(R1 + t * 256 + c), acc);
    g_rh[(size_t)r * 256 + c] = fmaxf(acc, 0.f);
}

// ---------------- epilogue helpers ----------------
__device__ __forceinline__ float blockReduce128(float v, volatile float* red) {
#pragma unroll
    for (int o = 16; o > 0; o >>= 1) v += __shfl_down_sync(0xffffffffu, v, o);
    __syncthreads();
    if ((threadIdx.x & 31) == 0) red[threadIdx.x >> 5] = v;
    __syncthreads();
    return red[0] + red[1] + red[2] + red[3];
}

__device__ __forceinline__ float focal_loss(float x, float t) {
    float p  = 1.0f / (1.0f + expf(-x));
    float ce = fmaxf(x, 0.0f) - x * t + log1pf(expf(-fabsf(x)));
    float pt = p * t + (1.0f - p) * (1.0f - t);
    float om = 1.0f - pt;
    float at = 0.25f * t + 0.75f * (1.0f - t);
    return at * ce * om * om;
}

// ---------------- per-row epilogue: norms, logits, focal, distil ----------------
__global__ void __launch_bounds__(128)
epilogue_kernel(const float* __restrict__ cw,
                const float* __restrict__ temp,
                const int* __restrict__ labels,
                const int* __restrict__ sids,
                const int* __restrict__ oids,
                const float* __restrict__ traj)
{
    const int r   = blockIdx.x;
    const int tid = threadIdx.x;
    __shared__ float sp[512];
    __shared__ float comb[512];
    __shared__ float red[4];
    __shared__ int   labsh[93];
    __shared__ int   s_pos;

    const int b = r / PPB;
    const int p = r - b * PPB;

    float ssp = 0.f, sre = 0.f;
    for (int k = tid; k < 512; k += 128) {
        float a = g_sp[(size_t)r * 512 + k];
        float e = g_re[(size_t)r * 512 + k];
        sp[k] = a; comb[k] = e;
        ssp += a * a; sre += e * e;
    }
    if (tid < 93) labsh[tid] = labels[(size_t)r * NLAB + tid];
    if (tid == 0) s_pos = 0;

    float tssp = blockReduce128(ssp, red);
    float tsre = blockReduce128(sre, red);
    float inv_sp = 1.f / fmaxf(sqrtf(tssp), 1e-12f);
    float inv_re = 1.f / fmaxf(sqrtf(tsre), 1e-12f);

    float ssc = 0.f;
    for (int k = tid; k < 512; k += 128) {
        float c = sp[k] * inv_sp + comb[k] * inv_re;
        comb[k] = c;
        ssc += c * c;
    }
    float tssc = blockReduce128(ssc, red);
    float inv_c = 1.f / fmaxf(sqrtf(tssc), 1e-12f);
    for (int k = tid; k < 512; k += 128) comb[k] *= inv_c;
    if (tid < NB && labsh[1 + tid] > 0) s_pos = 1;
    __syncthreads();

    const bool pos = (s_pos != 0);
    const bool neg = (labsh[0] > 0);
    const float inv_t = 1.0f / temp[0];

    float flp = 0.f, fln = 0.f;
    if (tid < NB) {
        const float4* w4 = reinterpret_cast<const float4*>(cw + (size_t)tid * 512);
        const float4* c4 = reinterpret_cast<const float4*>(comb);
        float x = 0.f;
#pragma unroll 4
        for (int k = 0; k < 128; k++) {
            float4 w = w4[k]; float4 c = c4[k];
            x += w.x * c.x + w.y * c.y + w.z * c.z + w.w * c.w;
        }
        x *= inv_t;
        float t = (float)labsh[1 + tid];
        flp = focal_loss(x, t);
        fln = focal_loss(x, 0.f);
    }

    const float* ts = traj + ((size_t)b * NDET + sids[p]) * 256;
    const float* to = traj + ((size_t)b * NDET + oids[p]) * 256;
    float d = 0.f;
    for (int k = tid; k < 256; k += 128) d += fabsf(ts[k] - sp[k]);
    for (int k = tid; k < 256; k += 128) d += fabsf(to[k] - sp[256 + k]);

    float tpos = blockReduce128(pos ? flp : 0.f, red);
    float tneg = blockReduce128(neg ? fln : 0.f, red);
    float td   = blockReduce128(d, red);

    if (tid == 0) {
        atomicAdd(&g_acc[0], (double)tpos);
        atomicAdd(&g_acc[1], (double)tneg);
        atomicAdd(&g_acc[2], (double)td);
        if (pos) atomicAdd(&g_cnt[0], 1u);
        if (neg) atomicAdd(&g_cnt[1], 1u);
    }
}

// ---------------- finalize ----------------
__global__ void finalize_kernel(float* __restrict__ out) {
    double pc = (double)(g_cnt[0] > 0u ? g_cnt[0] : 1u);
    double nc = (double)(g_cnt[1] > 0u ? g_cnt[1] : 1u);
    double total = g_acc[0] / (pc * (double)NB)
                 + g_acc[1] / (nc * (double)NB)
                 + g_acc[2] / ((double)MROWS * 512.0);
    out[0] = (float)total;
}

// ---------------- launch ----------------
#define GEMM_SMEM (4 * TILE_BYTES)   // 73728 bytes

extern "C" void kernel_launch(void* const* d_in, const int* in_sizes, int n_in,
                              void* d_out, int out_size)
{
    const float* det    = (const float*)d_in[0];
    const float* traj   = (const float*)d_in[1];
    const float* rp     = (const float*)d_in[2];
    const float* cw     = (const float*)d_in[3];
    const float* W1     = (const float*)d_in[4];
    const float* b1     = (const float*)d_in[5];
    const float* W2     = (const float*)d_in[6];
    const float* b2     = (const float*)d_in[7];
    const float* W3     = (const float*)d_in[8];
    const float* R1     = (const float*)d_in[9];
    const float* rb1    = (const float*)d_in[10];
    const float* R2     = (const float*)d_in[11];
    const float* temp   = (const float*)d_in[12];
    const int*   labels = (const int*)d_in[13];
    const int*   sids   = (const int*)d_in[14];
    const int*   oids   = (const int*)d_in[15];
    float* out = (float*)d_out;

    void *p_uv, *p_h2, *p_sp, *p_rh, *p_re, *p_w1u, *p_w1v, *p_w2t, *p_w3t, *p_r2t;
    cudaGetSymbolAddress(&p_uv, g_UV);
    cudaGetSymbolAddress(&p_h2, g_h2);
    cudaGetSymbolAddress(&p_sp, g_sp);
    cudaGetSymbolAddress(&p_rh, g_rh);
    cudaGetSymbolAddress(&p_re, g_re);
    cudaGetSymbolAddress(&p_w1u, g_W1tU);
    cudaGetSymbolAddress(&p_w1v, g_W1tV);
    cudaGetSymbolAddress(&p_w2t, g_W2t);
    cudaGetSymbolAddress(&p_w3t, g_W3t);
    cudaGetSymbolAddress(&p_r2t, g_R2t);
    float* UV  = (float*)p_uv;
    float* H2  = (float*)p_h2;
    float* SP  = (float*)p_sp;
    float* RH  = (float*)p_rh;
    float* RE  = (float*)p_re;
    float* W1U = (float*)p_w1u;
    float* W1V = (float*)p_w1v;
    float* W2T = (float*)p_w2t;
    float* W3T = (float*)p_w3t;
    float* R2T = (float*)p_r2t;

    cudaFuncSetAttribute(mma_gemm<0>, cudaFuncAttributeMaxDynamicSharedMemorySize, GEMM_SMEM);
    cudaFuncSetAttribute(mma_gemm<1>, cudaFuncAttributeMaxDynamicSharedMemorySize, GEMM_SMEM);

    init_acc_kernel<<<1, 1>>>();

    // weight transposes -> K-major
    transpose_kernel<<<dim3(1024 / 32, 2048 / 32), dim3(32, 8)>>>(W1,                       W1U, 2048, 1024);
    transpose_kernel<<<dim3(1024 / 32, 2048 / 32), dim3(32, 8)>>>(W1 + (size_t)2048 * 1024, W1V, 2048, 1024);
    transpose_kernel<<<dim3(1024 / 32, 1024 / 32), dim3(32, 8)>>>(W2, W2T, 1024, 1024);
    transpose_kernel<<<dim3(512  / 32, 1024 / 32), dim3(32, 8)>>>(W3, W3T, 1024, 512);
    transpose_kernel<<<dim3(512  / 32, 256  / 32), dim3(32, 8)>>>(R2, R2T, 256,  512);

    // U = det @ W1[:2048]  (C cols 0..1023 of g_UV)
    mma_gemm<0><<<dim3(8, 6), 256, GEMM_SMEM>>>(2048, det, 2048, W1U, UV,        2048,
                                                nullptr, nullptr, nullptr, nullptr);
    // V = det @ W1[2048:]  (C cols 1024..2047)
    mma_gemm<0><<<dim3(8, 6), 256, GEMM_SMEM>>>(2048, det, 2048, W1V, UV + 1024, 2048,
                                                nullptr, nullptr, nullptr, nullptr);
    // h2 = relu(relu(U_s + V_o + b1) @ W2 + b2)
    mma_gemm<1><<<dim3(8, MROWS / 128), 256, GEMM_SMEM>>>(1024, nullptr, 0, W2T, H2, 1024,
                                                          b1, b2, sids, oids);
    // so_proj = h2 @ W3
    mma_gemm<0><<<dim3(4, MROWS / 128), 256, GEMM_SMEM>>>(1024, H2, 1024, W3T, SP, 512,
                                                          nullptr, nullptr, nullptr, nullptr);
    // rh = relu(rp @ R1 + rb1)
    rh_kernel<<<MROWS, 256>>>(rp, R1, rb1);
    // re = rh @ R2
    mma_gemm<0><<<dim3(4, MROWS / 128), 256, GEMM_SMEM>>>(256, RH, 256, R2T, RE, 512,
                                                          nullptr, nullptr, nullptr, nullptr);

    epilogue_kernel<<<MROWS, 128>>>(cw, temp, labels, sids, oids, traj);
    finalize_kernel<<<1, 1>>>(out);
}

// round 4
// speedup vs baseline: 5.5358x; 1.9185x over previous
#include <cuda_runtime.h>
#include <math.h>
#include <cstdint>

// ---------------- problem constants ----------------
#define PPB   2256          // pairs per batch (48*47)
#define MROWS 36096         // BSZ * PPB
#define NDET  48
#define NB    92            // base classes
#define NLAB  133           // 1 + 92 + 40

// ---------------- scratch (__device__ globals; no allocations) ----------------
__device__ float g_UV[768 * 2048];                    // [768,2048]: cols 0..1023 = U, 1024..2047 = V
__device__ float g_h2[(size_t)MROWS * 1024];          // h2; later reused for logits [MROWS x 128]
__device__ float g_sp[(size_t)MROWS * 512];           // so_proj (raw)
__device__ float g_re[(size_t)MROWS * 512];           // re raw, then overwritten with normalized comb
__device__ float g_W1tU[1024 * 2048];
__device__ float g_W1tV[1024 * 2048];
__device__ float g_W2t[1024 * 1024];
__device__ float g_W3t[512 * 1024];
__device__ float g_R2t[512 * 256];
__device__ float g_cwp[128 * 512];                    // cw padded to 128 classes, tf32-rounded
__device__ double g_acc[3];
__device__ unsigned int g_cnt[2];

// ---------------- helpers ----------------
__device__ __forceinline__ uint32_t smem_to_u32(const void* p) {
    uint32_t a;
    asm("{ .reg .u64 t; cvta.to.shared.u64 t, %1; cvt.u32.u64 %0, t; }" : "=r"(a) : "l"(p));
    return a;
}
__device__ __forceinline__ float to_tf32(float x) {
    uint32_t u;
    asm("cvt.rna.tf32.f32 %0, %1;" : "=r"(u) : "f"(x));
    return __uint_as_float(u);
}
__device__ __forceinline__ void mma1688(float* d,
                                        uint32_t a0, uint32_t a1, uint32_t a2, uint32_t a3,
                                        uint32_t b0, uint32_t b1) {
    asm volatile(
        "mma.sync.aligned.m16n8k8.row.col.f32.tf32.tf32.f32 "
        "{%0,%1,%2,%3}, {%4,%5,%6,%7}, {%8,%9}, {%0,%1,%2,%3};"
        : "+f"(d[0]), "+f"(d[1]), "+f"(d[2]), "+f"(d[3])
        : "r"(a0), "r"(a1), "r"(a2), "r"(a3), "r"(b0), "r"(b1));
}
__device__ __forceinline__ void cp_async16(uint32_t saddr, const void* gaddr) {
    asm volatile("cp.async.cg.shared.global [%0], [%1], 16;" :: "r"(saddr), "l"(gaddr) : "memory");
}
#define CP_COMMIT()  asm volatile("cp.async.commit_group;" ::: "memory")
#define CP_WAIT1()   asm volatile("cp.async.wait_group 1;" ::: "memory")
#define CP_WAIT0()   asm volatile("cp.async.wait_group 0;" ::: "memory")

// ---------------- init ----------------
__global__ void init_acc_kernel() {
    g_acc[0] = 0.0; g_acc[1] = 0.0; g_acc[2] = 0.0;
    g_cnt[0] = 0u;  g_cnt[1] = 0u;
}

// ---------------- weight transpose: dst[n][k] = tf32(src[k][n]) ----------------
__global__ void __launch_bounds__(256)
transpose_kernel(const float* __restrict__ src, float* __restrict__ dst, int K, int N)
{
    __shared__ float t[32][33];
    int kb = blockIdx.y * 32, nb = blockIdx.x * 32;
    int x = threadIdx.x, y = threadIdx.y;
#pragma unroll
    for (int i = y; i < 32; i += 8) t[i][x] = src[(size_t)(kb + i) * N + nb + x];
    __syncthreads();
#pragma unroll
    for (int i = y; i < 32; i += 8) dst[(size_t)(nb + i) * K + kb + x] = to_tf32(t[x][i]);
}

// ---------------- pad + round classifier: cwp[128][512] ----------------
__global__ void __launch_bounds__(256)
pad_cw_kernel(const float* __restrict__ cw)
{
    int i = blockIdx.x * 256 + threadIdx.x;     // 0..65535
    int n = i >> 9, k = i & 511;
    g_cwp[i] = (n < NB) ? to_tf32(cw[(size_t)n * 512 + k]) : 0.f;
}

// =====================================================================
// tf32 mma.sync GEMM: C[128x128 tile] = A[M,K] (row-major) x Bt[N,K]^T
// MODE 0: A from global (LDG+rna), passthrough epilogue.
// MODE 1: A = relu(U[urow]+V[vrow]+b1) from g_UV; epilogue relu(x+b2), rounded.
// MODE 2: A = relu(rp @ R1 + rb1) computed on the fly (params: A=rp, b1=R1, b2=rb1).
// B tiles: cp.async double-buffered (weights pre-rounded to tf32).
// =====================================================================
#define APAD 36
#define TILE_BYTES (128 * APAD * 4)      // 18432, row stride 144B (16B-aligned)

template<int MODE>
__global__ void __launch_bounds__(256, 1)
mma_gemm(int K,
         const float* __restrict__ A, int lda,
         const float* __restrict__ Bt,
         float* __restrict__ C, int ldc,
         const float* __restrict__ b1, const float* __restrict__ b2,
         const int* __restrict__ sids, const int* __restrict__ oids)
{
    extern __shared__ char smem[];
    __shared__ int urow[128], vrow[128];
    __shared__ float rps[128 * 12];

    const int tid  = threadIdx.x;
    const int wid  = tid >> 5;
    const int lane = tid & 31;
    const int rowBlk = blockIdx.y * 128;
    const int colBlk = blockIdx.x * 128;

    const int wm = (wid & 1) * 64;
    const int wn = (wid >> 1) * 32;
    const int g  = lane >> 2;
    const int tg = lane & 3;

    if (MODE == 1) {
        if (tid < 128) {
            int r = rowBlk + tid;
            int b = r / PPB, p = r - b * PPB;
            urow[tid] = b * NDET + sids[p];
            vrow[tid] = b * NDET + oids[p];
        }
        __syncthreads();
    }
    if (MODE == 2) {
        for (int idx = tid; idx < 128 * 12; idx += 256)
            rps[idx] = A[(size_t)rowBlk * 12 + idx];
        __syncthreads();
    }

    float* AsBase = reinterpret_cast<float*>(smem);
    float* BsBase = reinterpret_cast<float*>(smem + 2 * TILE_BYTES);
    const uint32_t sbB = smem_to_u32(BsBase);

    float acc[4][4][4];
#pragma unroll
    for (int i = 0; i < 4; i++)
#pragma unroll
        for (int j = 0; j < 4; j++)
#pragma unroll
            for (int q = 0; q < 4; q++) acc[i][j][q] = 0.f;

    float4 ra[4], rav[4];
    int amr[4], aq[4];
#pragma unroll
    for (int j = 0; j < 4; ++j) {
        int idx = tid + j * 256;
        amr[j] = idx >> 3;
        aq[j]  = idx & 7;
    }

    auto loadA = [&](int c) {
        const int k0 = c * 32;
#pragma unroll
        for (int j = 0; j < 4; ++j) {
            const int m = amr[j], q = aq[j];
            if (MODE == 1) {
                ra[j]  = *reinterpret_cast<const float4*>(&g_UV[(size_t)urow[m] * 2048 + k0 + q * 4]);
                rav[j] = *reinterpret_cast<const float4*>(&g_UV[(size_t)vrow[m] * 2048 + 1024 + k0 + q * 4]);
            } else if (MODE == 2) {
                float4 a = *reinterpret_cast<const float4*>(b2 + k0 + q * 4);   // rb1
#pragma unroll
                for (int t = 0; t < 12; ++t) {
                    const float xv = rps[m * 12 + t];
                    const float4 w = *reinterpret_cast<const float4*>(b1 + t * 256 + k0 + q * 4); // R1
                    a.x = fmaf(xv, w.x, a.x); a.y = fmaf(xv, w.y, a.y);
                    a.z = fmaf(xv, w.z, a.z); a.w = fmaf(xv, w.w, a.w);
                }
                a.x = fmaxf(a.x, 0.f); a.y = fmaxf(a.y, 0.f);
                a.z = fmaxf(a.z, 0.f); a.w = fmaxf(a.w, 0.f);
                ra[j] = a;
            } else {
                ra[j] = *reinterpret_cast<const float4*>(A + (size_t)(rowBlk + m) * lda + k0 + q * 4);
            }
        }
    };
    auto issueB = [&](int s, int c) {
        const int k0 = c * 32;
#pragma unroll
        for (int j = 0; j < 4; ++j) {
            const int m = amr[j], q = aq[j];
            cp_async16(sbB + (uint32_t)s * TILE_BYTES + (uint32_t)m * (APAD * 4) + (uint32_t)q * 16,
                       Bt + (size_t)(colBlk + m) * K + k0 + q * 4);
        }
        CP_COMMIT();
    };
    auto storeA = [&](int s, int c) {
        float* As = AsBase + s * (TILE_BYTES / 4);
        const int k0 = c * 32;
#pragma unroll
        for (int j = 0; j < 4; ++j) {
            const int m = amr[j], q = aq[j];
            float4 av = ra[j];
            if (MODE == 1) {
                const float4 vv = rav[j];
                const float4 bb = *reinterpret_cast<const float4*>(b1 + k0 + q * 4);
                av.x = fmaxf(av.x + vv.x + bb.x, 0.f);
                av.y = fmaxf(av.y + vv.y + bb.y, 0.f);
                av.z = fmaxf(av.z + vv.z + bb.z, 0.f);
                av.w = fmaxf(av.w + vv.w + bb.w, 0.f);
            }
            av.x = to_tf32(av.x); av.y = to_tf32(av.y);
            av.z = to_tf32(av.z); av.w = to_tf32(av.w);
            *reinterpret_cast<float4*>(&As[m * APAD + q * 4]) = av;
        }
    };
    auto compute = [&](int s) {
        const float* As = AsBase + s * (TILE_BYTES / 4);
        const float* Bs = BsBase + s * (TILE_BYTES / 4);
#pragma unroll
        for (int ks = 0; ks < 4; ++ks) {
            const int k = ks * 8;
            uint32_t a[4][4], b[4][2];
#pragma unroll
            for (int mt = 0; mt < 4; ++mt) {
                const int r0 = wm + mt * 16;
                a[mt][0] = __float_as_uint(As[(r0 + g)     * APAD + k + tg]);
                a[mt][1] = __float_as_uint(As[(r0 + g + 8) * APAD + k + tg]);
                a[mt][2] = __float_as_uint(As[(r0 + g)     * APAD + k + tg + 4]);
                a[mt][3] = __float_as_uint(As[(r0 + g + 8) * APAD + k + tg + 4]);
            }
#pragma unroll
            for (int nt = 0; nt < 4; ++nt) {
                const int n0 = wn + nt * 8;
                b[nt][0] = __float_as_uint(Bs[(n0 + g) * APAD + k + tg]);
                b[nt][1] = __float_as_uint(Bs[(n0 + g) * APAD + k + tg + 4]);
            }
#pragma unroll
            for (int mt = 0; mt < 4; ++mt)
#pragma unroll
                for (int nt = 0; nt < 4; ++nt)
                    mma1688(acc[mt][nt], a[mt][0], a[mt][1], a[mt][2], a[mt][3],
                            b[nt][0], b[nt][1]);
        }
    };

    const int nch = K >> 5;
    loadA(0);
    issueB(0, 0);
    storeA(0, 0);
    int cur = 0;
    for (int c = 0; c < nch; ++c) {
        const bool more = (c + 1 < nch);
        if (more) { loadA(c + 1); issueB(cur ^ 1, c + 1); }
        if (more) { CP_WAIT1(); } else { CP_WAIT0(); }
        __syncthreads();
        compute(cur);
        if (more) storeA(cur ^ 1, c + 1);
        __syncthreads();
        cur ^= 1;
    }

    // ---- epilogue ----
#pragma unroll
    for (int mt = 0; mt < 4; ++mt) {
#pragma unroll
        for (int nt = 0; nt < 4; ++nt) {
            const int col = colBlk + wn + nt * 8 + 2 * tg;
            float2 v0 = make_float2(acc[mt][nt][0], acc[mt][nt][1]);
            float2 v1 = make_float2(acc[mt][nt][2], acc[mt][nt][3]);
            if (MODE == 1) {
                const float2 bb = *reinterpret_cast<const float2*>(b2 + col);
                v0.x = to_tf32(fmaxf(v0.x + bb.x, 0.f)); v0.y = to_tf32(fmaxf(v0.y + bb.y, 0.f));
                v1.x = to_tf32(fmaxf(v1.x + bb.x, 0.f)); v1.y = to_tf32(fmaxf(v1.y + bb.y, 0.f));
            }
            const int row0 = rowBlk + wm + mt * 16 + g;
            *reinterpret_cast<float2*>(C + (size_t)row0 * ldc + col)       = v0;
            *reinterpret_cast<float2*>(C + (size_t)(row0 + 8) * ldc + col) = v1;
        }
    }
}

// ---------------- reductions ----------------
__device__ __forceinline__ float blockReduce128(float v, volatile float* red) {
#pragma unroll
    for (int o = 16; o > 0; o >>= 1) v += __shfl_down_sync(0xffffffffu, v, o);
    __syncthreads();
    if ((threadIdx.x & 31) == 0) red[threadIdx.x >> 5] = v;
    __syncthreads();
    return red[0] + red[1] + red[2] + red[3];
}

__device__ __forceinline__ float focal_loss(float x, float t) {
    float p  = 1.0f / (1.0f + expf(-x));
    float ce = fmaxf(x, 0.0f) - x * t + log1pf(expf(-fabsf(x)));
    float pt = p * t + (1.0f - p) * (1.0f - t);
    float om = 1.0f - pt;
    float at = 0.25f * t + 0.75f * (1.0f - t);
    return at * ce * om * om;
}

// ---------------- normalize + distil: comb -> g_re (tf32-rounded) ----------------
__global__ void __launch_bounds__(128)
normalize_kernel(const float* __restrict__ traj,
                 const int* __restrict__ sids,
                 const int* __restrict__ oids)
{
    const int r   = blockIdx.x;
    const int tid = threadIdx.x;
    __shared__ float sp[512];
    __shared__ float comb[512];
    __shared__ float red[4];

    const int b = r / PPB;
    const int p = r - b * PPB;

    float ssp = 0.f, sre = 0.f;
    for (int k = tid; k < 512; k += 128) {
        float a = g_sp[(size_t)r * 512 + k];
        float e = g_re[(size_t)r * 512 + k];
        sp[k] = a; comb[k] = e;
        ssp += a * a; sre += e * e;
    }
    float tssp = blockReduce128(ssp, red);
    float tsre = blockReduce128(sre, red);
    float inv_sp = 1.f / fmaxf(sqrtf(tssp), 1e-12f);
    float inv_re = 1.f / fmaxf(sqrtf(tsre), 1e-12f);

    float ssc = 0.f;
    for (int k = tid; k < 512; k += 128) {
        float c = sp[k] * inv_sp + comb[k] * inv_re;
        comb[k] = c;
        ssc += c * c;
    }
    float tssc = blockReduce128(ssc, red);
    float inv_c = 1.f / fmaxf(sqrtf(tssc), 1e-12f);
    for (int k = tid; k < 512; k += 128)
        g_re[(size_t)r * 512 + k] = to_tf32(comb[k] * inv_c);

    const float* ts = traj + ((size_t)b * NDET + sids[p]) * 256;
    const float* to = traj + ((size_t)b * NDET + oids[p]) * 256;
    float d = 0.f;
    for (int k = tid; k < 256; k += 128) d += fabsf(ts[k] - sp[k]);
    for (int k = tid; k < 256; k += 128) d += fabsf(to[k] - sp[256 + k]);
    float td = blockReduce128(d, red);
    if (tid == 0) atomicAdd(&g_acc[2], (double)td);
}

// ---------------- focal reduction over logits (g_h2 holds [MROWS x 128]) ----------------
__global__ void __launch_bounds__(128)
focal_kernel(const float* __restrict__ temp,
             const int* __restrict__ labels)
{
    const int r   = blockIdx.x;
    const int tid = threadIdx.x;
    __shared__ int   labsh[93];
    __shared__ int   s_pos;
    __shared__ float red[4];

    if (tid == 0) s_pos = 0;
    if (tid < 93) labsh[tid] = labels[(size_t)r * NLAB + tid];
    __syncthreads();
    if (tid < NB && labsh[1 + tid] > 0) s_pos = 1;
    __syncthreads();

    const bool pos = (s_pos != 0);
    const bool neg = (labsh[0] > 0);
    const float inv_t = 1.0f / temp[0];

    float flp = 0.f, fln = 0.f;
    if (tid < NB) {
        float x = g_h2[(size_t)r * 128 + tid] * inv_t;
        float t = (float)labsh[1 + tid];
        flp = focal_loss(x, t);
        fln = focal_loss(x, 0.f);
    }
    float tpos = blockReduce128(pos ? flp : 0.f, red);
    float tneg = blockReduce128(neg ? fln : 0.f, red);
    if (tid == 0) {
        atomicAdd(&g_acc[0], (double)tpos);
        atomicAdd(&g_acc[1], (double)tneg);
        if (pos) atomicAdd(&g_cnt[0], 1u);
        if (neg) atomicAdd(&g_cnt[1], 1u);
    }
}

// ---------------- finalize ----------------
__global__ void finalize_kernel(float* __restrict__ out) {
    double pc = (double)(g_cnt[0] > 0u ? g_cnt[0] : 1u);
    double nc = (double)(g_cnt[1] > 0u ? g_cnt[1] : 1u);
    double total = g_acc[0] / (pc * (double)NB)
                 + g_acc[1] / (nc * (double)NB)
                 + g_acc[2] / ((double)MROWS * 512.0);
    out[0] = (float)total;
}

// ---------------- launch ----------------
#define GEMM_SMEM (4 * TILE_BYTES)   // 73728 bytes

extern "C" void kernel_launch(void* const* d_in, const int* in_sizes, int n_in,
                              void* d_out, int out_size)
{
    const float* det    = (const float*)d_in[0];
    const float* traj   = (const float*)d_in[1];
    const float* rp     = (const float*)d_in[2];
    const float* cw     = (const float*)d_in[3];
    const float* W1     = (const float*)d_in[4];
    const float* b1     = (const float*)d_in[5];
    const float* W2     = (const float*)d_in[6];
    const float* b2     = (const float*)d_in[7];
    const float* W3     = (const float*)d_in[8];
    const float* R1     = (const float*)d_in[9];
    const float* rb1    = (const float*)d_in[10];
    const float* R2     = (const float*)d_in[11];
    const float* temp   = (const float*)d_in[12];
    const int*   labels = (const int*)d_in[13];
    const int*   sids   = (const int*)d_in[14];
    const int*   oids   = (const int*)d_in[15];
    float* out = (float*)d_out;

    void *p_uv, *p_h2, *p_sp, *p_re, *p_w1u, *p_w1v, *p_w2t, *p_w3t, *p_r2t, *p_cwp;
    cudaGetSymbolAddress(&p_uv, g_UV);
    cudaGetSymbolAddress(&p_h2, g_h2);
    cudaGetSymbolAddress(&p_sp, g_sp);
    cudaGetSymbolAddress(&p_re, g_re);
    cudaGetSymbolAddress(&p_w1u, g_W1tU);
    cudaGetSymbolAddress(&p_w1v, g_W1tV);
    cudaGetSymbolAddress(&p_w2t, g_W2t);
    cudaGetSymbolAddress(&p_w3t, g_W3t);
    cudaGetSymbolAddress(&p_r2t, g_R2t);
    cudaGetSymbolAddress(&p_cwp, g_cwp);
    float* UV  = (float*)p_uv;
    float* H2  = (float*)p_h2;
    float* SP  = (float*)p_sp;
    float* RE  = (float*)p_re;
    float* W1U = (float*)p_w1u;
    float* W1V = (float*)p_w1v;
    float* W2T = (float*)p_w2t;
    float* W3T = (float*)p_w3t;
    float* R2T = (float*)p_r2t;
    float* CWP = (float*)p_cwp;

    cudaFuncSetAttribute(mma_gemm<0>, cudaFuncAttributeMaxDynamicSharedMemorySize, GEMM_SMEM);
    cudaFuncSetAttribute(mma_gemm<1>, cudaFuncAttributeMaxDynamicSharedMemorySize, GEMM_SMEM);
    cudaFuncSetAttribute(mma_gemm<2>, cudaFuncAttributeMaxDynamicSharedMemorySize, GEMM_SMEM);

    init_acc_kernel<<<1, 1>>>();

    // weight prep (tf32-rounded, K-major)
    transpose_kernel<<<dim3(1024 / 32, 2048 / 32), dim3(32, 8)>>>(W1,                       W1U, 2048, 1024);
    transpose_kernel<<<dim3(1024 / 32, 2048 / 32), dim3(32, 8)>>>(W1 + (size_t)2048 * 1024, W1V, 2048, 1024);
    transpose_kernel<<<dim3(1024 / 32, 1024 / 32), dim3(32, 8)>>>(W2, W2T, 1024, 1024);
    transpose_kernel<<<dim3(512  / 32, 1024 / 32), dim3(32, 8)>>>(W3, W3T, 1024, 512);
    transpose_kernel<<<dim3(512  / 32, 256  / 32), dim3(32, 8)>>>(R2, R2T, 256,  512);
    pad_cw_kernel<<<256, 256>>>(cw);

    // U = det @ W1[:2048], V = det @ W1[2048:]
    mma_gemm<0><<<dim3(8, 6), 256, GEMM_SMEM>>>(2048, det, 2048, W1U, UV,        2048,
                                                nullptr, nullptr, nullptr, nullptr);
    mma_gemm<0><<<dim3(8, 6), 256, GEMM_SMEM>>>(2048, det, 2048, W1V, UV + 1024, 2048,
                                                nullptr, nullptr, nullptr, nullptr);
    // h2 = relu(relu(U_s + V_o + b1) @ W2 + b2)
    mma_gemm<1><<<dim3(8, MROWS / 128), 256, GEMM_SMEM>>>(1024, nullptr, 0, W2T, H2, 1024,
                                                          b1, b2, sids, oids);
    // so_proj = h2 @ W3
    mma_gemm<0><<<dim3(4, MROWS / 128), 256, GEMM_SMEM>>>(1024, H2, 1024, W3T, SP, 512,
                                                          nullptr, nullptr, nullptr, nullptr);
    // re = relu(rp @ R1 + rb1) @ R2   (rh fused into A-feed)
    mma_gemm<2><<<dim3(4, MROWS / 128), 256, GEMM_SMEM>>>(256, rp, 12, R2T, RE, 512,
                                                          R1, rb1, nullptr, nullptr);
    // norms + distil; comb -> g_re
    normalize_kernel<<<MROWS, 128>>>(traj, sids, oids);
    // logits = comb @ cwp^T  -> g_h2[:, :128]
    mma_gemm<0><<<dim3(1, MROWS / 128), 256, GEMM_SMEM>>>(512, RE, 512, CWP, H2, 128,
                                                          nullptr, nullptr, nullptr, nullptr);
    // focal reduction
    focal_kernel<<<MROWS, 128>>>(temp, labels);
    finalize_kernel<<<1, 1>>>(out);
}

// round 5
// speedup vs baseline: 5.8128x; 1.0500x over previous
#include <cuda_runtime.h>
#include <math.h>
#include <cstdint>

// ---------------- problem constants ----------------
#define PPB   2256
#define MROWS 36096
#define NDET  48
#define NB    92
#define NLAB  133

// ---------------- scratch ----------------
__device__ float g_det[768 * 2048];                   // tf32-rounded det_feats
__device__ float g_UV[768 * 2048];
__device__ float g_h2[(size_t)MROWS * 1024];
__device__ float g_sp[(size_t)MROWS * 512];
__device__ float g_re[(size_t)MROWS * 512];
__device__ float g_W1tU[1024 * 2048];
__device__ float g_W1tV[1024 * 2048];
__device__ float g_W2t[1024 * 1024];
__device__ float g_W3t[512 * 1024];
__device__ float g_R2t[512 * 256];
__device__ float g_cwp[128 * 512];
__device__ double g_acc[3];
__device__ unsigned int g_cnt[2];

// ---------------- helpers ----------------
__device__ __forceinline__ uint32_t smem_to_u32(const void* p) {
    uint32_t a;
    asm("{ .reg .u64 t; cvta.to.shared.u64 t, %1; cvt.u32.u64 %0, t; }" : "=r"(a) : "l"(p));
    return a;
}
__device__ __forceinline__ float to_tf32(float x) {
    uint32_t u;
    asm("cvt.rna.tf32.f32 %0, %1;" : "=r"(u) : "f"(x));
    return __uint_as_float(u);
}
__device__ __forceinline__ void mma1688(float* d,
                                        uint32_t a0, uint32_t a1, uint32_t a2, uint32_t a3,
                                        uint32_t b0, uint32_t b1) {
    asm volatile(
        "mma.sync.aligned.m16n8k8.row.col.f32.tf32.tf32.f32 "
        "{%0,%1,%2,%3}, {%4,%5,%6,%7}, {%8,%9}, {%0,%1,%2,%3};"
        : "+f"(d[0]), "+f"(d[1]), "+f"(d[2]), "+f"(d[3])
        : "r"(a0), "r"(a1), "r"(a2), "r"(a3), "r"(b0), "r"(b1));
}
__device__ __forceinline__ void ldsm_x4(uint32_t* r, uint32_t saddr) {
    asm volatile("ldmatrix.sync.aligned.m8n8.x4.shared.b16 {%0,%1,%2,%3}, [%4];"
                 : "=r"(r[0]), "=r"(r[1]), "=r"(r[2]), "=r"(r[3]) : "r"(saddr));
}
__device__ __forceinline__ void cp_async16(uint32_t saddr, const void* gaddr) {
    asm volatile("cp.async.cg.shared.global [%0], [%1], 16;" :: "r"(saddr), "l"(gaddr) : "memory");
}
#define CP_COMMIT()  asm volatile("cp.async.commit_group;" ::: "memory")
#define CP_WAIT1()   asm volatile("cp.async.wait_group 1;" ::: "memory")

// ---------------- init / prep ----------------
__global__ void init_acc_kernel() {
    g_acc[0] = 0.0; g_acc[1] = 0.0; g_acc[2] = 0.0;
    g_cnt[0] = 0u;  g_cnt[1] = 0u;
}
__global__ void __launch_bounds__(256)
round_kernel(const float* __restrict__ src, float* __restrict__ dst, int n) {
    int i = blockIdx.x * 256 + threadIdx.x;
    if (i < n) dst[i] = to_tf32(src[i]);
}
__global__ void __launch_bounds__(256)
transpose_kernel(const float* __restrict__ src, float* __restrict__ dst, int K, int N)
{
    __shared__ float t[32][33];
    int kb = blockIdx.y * 32, nb = blockIdx.x * 32;
    int x = threadIdx.x, y = threadIdx.y;
#pragma unroll
    for (int i = y; i < 32; i += 8) t[i][x] = src[(size_t)(kb + i) * N + nb + x];
    __syncthreads();
#pragma unroll
    for (int i = y; i < 32; i += 8) dst[(size_t)(nb + i) * K + kb + x] = to_tf32(t[x][i]);
}
__global__ void __launch_bounds__(256)
pad_cw_kernel(const float* __restrict__ cw)
{
    int i = blockIdx.x * 256 + threadIdx.x;
    int n = i >> 9, k = i & 511;
    g_cwp[i] = (n < NB) ? to_tf32(cw[(size_t)n * 512 + k]) : 0.f;
}

__device__ __forceinline__ float focal_loss(float x, float t) {
    float p  = 1.0f / (1.0f + expf(-x));
    float ce = fmaxf(x, 0.0f) - x * t + log1pf(expf(-fabsf(x)));
    float pt = p * t + (1.0f - p) * (1.0f - t);
    float om = 1.0f - pt;
    float at = 0.25f * t + 0.75f * (1.0f - t);
    return at * ce * om * om;
}

// =====================================================================
// tf32 mma.sync GEMM with ldmatrix feed + 3-stage cp.async pipeline.
// MODE 0: A via cp.async (pre-rounded tf32 in gmem), plain epilogue -> C.
// MODE 1: A = relu(U[urow]+V[vrow]+b1) (register-staged); epi relu(+b2), rounded.
// MODE 2: A = relu(rp @ R1 + rb1) computed on the fly (A=rp, b1=R1, b2=rb1).
// MODE 3: like 0 but N=128 single tile; epilogue = focal loss reduction.
// =====================================================================
#define APAD 36
#define TROWB 144                         // bytes per tile row
#define TILE_BYTES (128 * TROWB)          // 18432
#define NSTAGE 3
#define GEMM_SMEM (2 * NSTAGE * TILE_BYTES)   // 110592

template<int MODE>
__global__ void __launch_bounds__(256, 1)
mma_gemm(int K,
         const float* __restrict__ A, int lda,
         const float* __restrict__ Bt,
         float* __restrict__ C, int ldc,
         const float* __restrict__ b1, const float* __restrict__ b2,
         const int* __restrict__ sids, const int* __restrict__ oids,
         const int* __restrict__ labels, const float* __restrict__ temp)
{
    extern __shared__ char smem[];
    __shared__ int urow[128], vrow[128];
    __shared__ float rps[128 * 12];
    __shared__ float wredP[8], wredN[8];
    __shared__ int   wpc[8], wnc[8];

    const int tid  = threadIdx.x;
    const int wid  = tid >> 5;
    const int lane = tid & 31;
    const int rowBlk = blockIdx.y * 128;
    const int colBlk = blockIdx.x * 128;

    const int wm = (wid & 1) * 64;
    const int wn = (wid >> 1) * 32;
    const int g  = lane >> 2;
    const int tg = lane & 3;

    const uint32_t sb  = smem_to_u32(smem);
    const uint32_t sbA = sb;
    const uint32_t sbB = sb + NSTAGE * TILE_BYTES;

    if (MODE == 1) {
        if (tid < 128) {
            int r = rowBlk + tid;
            int b = r / PPB, p = r - b * PPB;
            urow[tid] = b * NDET + sids[p];
            vrow[tid] = b * NDET + oids[p];
        }
        __syncthreads();
    }
    if (MODE == 2) {
        for (int idx = tid; idx < 128 * 12; idx += 256)
            rps[idx] = A[(size_t)rowBlk * 12 + idx];
        __syncthreads();
    }

    float acc[4][4][4];
#pragma unroll
    for (int i = 0; i < 4; i++)
#pragma unroll
        for (int j = 0; j < 4; j++)
#pragma unroll
            for (int q = 0; q < 4; q++) acc[i][j][q] = 0.f;

    int amr[4], aq[4];
#pragma unroll
    for (int j = 0; j < 4; ++j) {
        int idx = tid + j * 256;
        amr[j] = idx >> 3;
        aq[j]  = idx & 7;
    }

    float4 ra[4], rav[4];   // A staging (MODE 1/2)

    auto loadA = [&](int c) {
        const int k0 = c * 32;
#pragma unroll
        for (int j = 0; j < 4; ++j) {
            const int m = amr[j], q = aq[j];
            if (MODE == 1) {
                ra[j]  = *reinterpret_cast<const float4*>(&g_UV[(size_t)urow[m] * 2048 + k0 + q * 4]);
                rav[j] = *reinterpret_cast<const float4*>(&g_UV[(size_t)vrow[m] * 2048 + 1024 + k0 + q * 4]);
            } else if (MODE == 2) {
                float4 a = *reinterpret_cast<const float4*>(b2 + k0 + q * 4);   // rb1
#pragma unroll
                for (int t = 0; t < 12; ++t) {
                    const float xv = rps[m * 12 + t];
                    const float4 w = *reinterpret_cast<const float4*>(b1 + t * 256 + k0 + q * 4); // R1
                    a.x = fmaf(xv, w.x, a.x); a.y = fmaf(xv, w.y, a.y);
                    a.z = fmaf(xv, w.z, a.z); a.w = fmaf(xv, w.w, a.w);
                }
                a.x = fmaxf(a.x, 0.f); a.y = fmaxf(a.y, 0.f);
                a.z = fmaxf(a.z, 0.f); a.w = fmaxf(a.w, 0.f);
                ra[j] = a;
            }
        }
    };
    auto storeA = [&](int c, int s) {
        float* As = reinterpret_cast<float*>(smem + s * TILE_BYTES);
        const int k0 = c * 32;
#pragma unroll
        for (int j = 0; j < 4; ++j) {
            const int m = amr[j], q = aq[j];
            float4 av = ra[j];
            if (MODE == 1) {
                const float4 vv = rav[j];
                const float4 bb = *reinterpret_cast<const float4*>(b1 + k0 + q * 4);
                av.x = fmaxf(av.x + vv.x + bb.x, 0.f);
                av.y = fmaxf(av.y + vv.y + bb.y, 0.f);
                av.z = fmaxf(av.z + vv.z + bb.z, 0.f);
                av.w = fmaxf(av.w + vv.w + bb.w, 0.f);
            }
            av.x = to_tf32(av.x); av.y = to_tf32(av.y);
            av.z = to_tf32(av.z); av.w = to_tf32(av.w);
            *reinterpret_cast<float4*>(&As[m * APAD + q * 4]) = av;
        }
    };
    auto issueLoads = [&](int c, int s) {
        const int k0 = c * 32;
#pragma unroll
        for (int j = 0; j < 4; ++j) {
            const int m = amr[j], q = aq[j];
            cp_async16(sbB + (uint32_t)s * TILE_BYTES + (uint32_t)m * TROWB + (uint32_t)q * 16,
                       Bt + (size_t)(colBlk + m) * K + k0 + q * 4);
            if (MODE == 0 || MODE == 3)
                cp_async16(sbA + (uint32_t)s * TILE_BYTES + (uint32_t)m * TROWB + (uint32_t)q * 16,
                           A + (size_t)(rowBlk + m) * lda + k0 + q * 4);
        }
    };

    // per-lane ldmatrix addressing: lane -> (row within 16-row group, col group)
    const int laneRow  = lane & 15;              // rows 0..15 of fragment tile
    const int laneColB = (lane >> 4) * 16;       // 0 or 16 bytes (4 floats)
    const uint32_t aFragBase = sbA + (uint32_t)(wm + laneRow) * TROWB + laneColB;
    const uint32_t bFragBase = sbB + (uint32_t)(wn + laneRow) * TROWB + laneColB;

    auto compute = [&](int s) {
        const uint32_t aB = aFragBase + (uint32_t)s * TILE_BYTES;
        const uint32_t bB = bFragBase + (uint32_t)s * TILE_BYTES;
#pragma unroll
        for (int ks = 0; ks < 4; ++ks) {
            const uint32_t ko = (uint32_t)ks * 32;
            uint32_t a[4][4], bb[2][4];
#pragma unroll
            for (int mt = 0; mt < 4; ++mt) ldsm_x4(a[mt], aB + (uint32_t)mt * 2304 + ko);
#pragma unroll
            for (int n2 = 0; n2 < 2; ++n2)  ldsm_x4(bb[n2], bB + (uint32_t)n2 * 2304 + ko);
#pragma unroll
            for (int mt = 0; mt < 4; ++mt)
#pragma unroll
                for (int nt = 0; nt < 4; ++nt)
                    mma1688(acc[mt][nt], a[mt][0], a[mt][1], a[mt][2], a[mt][3],
                            bb[nt >> 1][nt & 1], bb[nt >> 1][2 + (nt & 1)]);
        }
    };

    const int nch = K >> 5;   // always >= 8 here

    // prologue: fill stages 0 and 1
    if (MODE == 1 || MODE == 2) loadA(0);
    issueLoads(0, 0); CP_COMMIT();
    if (MODE == 1 || MODE == 2) { storeA(0, 0); loadA(1); }
    issueLoads(1, 1); CP_COMMIT();
    CP_WAIT1();
    __syncthreads();

    for (int c = 0; c < nch; ++c) {
        const int s = c % 3;
        if (MODE == 1 || MODE == 2) {
            if (c + 1 < nch) storeA(c + 1, (c + 1) % 3);
            if (c + 2 < nch) { loadA(c + 2); issueLoads(c + 2, (c + 2) % 3); }
        } else {
            if (c + 2 < nch) issueLoads(c + 2, (c + 2) % 3);
        }
        CP_COMMIT();
        compute(s);
        CP_WAIT1();
        __syncthreads();
    }

    if (MODE != 3) {
        // ---- epilogue: direct float2 stores ----
#pragma unroll
        for (int mt = 0; mt < 4; ++mt) {
#pragma unroll
            for (int nt = 0; nt < 4; ++nt) {
                const int col = colBlk + wn + nt * 8 + 2 * tg;
                float2 v0 = make_float2(acc[mt][nt][0], acc[mt][nt][1]);
                float2 v1 = make_float2(acc[mt][nt][2], acc[mt][nt][3]);
                if (MODE == 1) {
                    const float2 bb = *reinterpret_cast<const float2*>(b2 + col);
                    v0.x = to_tf32(fmaxf(v0.x + bb.x, 0.f)); v0.y = to_tf32(fmaxf(v0.y + bb.y, 0.f));
                    v1.x = to_tf32(fmaxf(v1.x + bb.x, 0.f)); v1.y = to_tf32(fmaxf(v1.y + bb.y, 0.f));
                }
                const int row0 = rowBlk + wm + mt * 16 + g;
                *reinterpret_cast<float2*>(C + (size_t)row0 * ldc + col)       = v0;
                *reinterpret_cast<float2*>(C + (size_t)(row0 + 8) * ldc + col) = v1;
            }
        }
    } else {
        // ---- MODE 3: stage logits in smem, fused focal reduction ----
        float* stageL = reinterpret_cast<float*>(smem);    // [128][132]
#pragma unroll
        for (int mt = 0; mt < 4; ++mt) {
#pragma unroll
            for (int nt = 0; nt < 4; ++nt) {
                const int col = wn + nt * 8 + 2 * tg;
                const int r0  = wm + mt * 16 + g;
                *reinterpret_cast<float2*>(&stageL[r0 * 132 + col]) =
                    make_float2(acc[mt][nt][0], acc[mt][nt][1]);
                *reinterpret_cast<float2*>(&stageL[(r0 + 8) * 132 + col]) =
                    make_float2(acc[mt][nt][2], acc[mt][nt][3]);
            }
        }
        __syncthreads();

        const float inv_t = 1.0f / temp[0];
        float flp = 0.f, fln = 0.f;
        int pc = 0, nc = 0;
#pragma unroll 1
        for (int i = 0; i < 16; ++i) {
            const int r = wid * 16 + i;
            const int* lab = labels + (size_t)(rowBlk + r) * NLAB;
            const int l0 = lab[0];
            float fp = 0.f, fn = 0.f;
            bool any = false;
            for (int c = lane; c < NB; c += 32) {
                const int t = lab[1 + c];
                const float x = stageL[r * 132 + c] * inv_t;
                fp += focal_loss(x, (float)t);
                fn += focal_loss(x, 0.f);
                any |= (t > 0);
            }
#pragma unroll
            for (int o = 16; o > 0; o >>= 1) {
                fp += __shfl_xor_sync(0xffffffffu, fp, o);
                fn += __shfl_xor_sync(0xffffffffu, fn, o);
            }
            const bool pos = __any_sync(0xffffffffu, any);
            const bool neg = (l0 > 0);
            if (lane == 0) {
                if (pos) { flp += fp; pc++; }
                if (neg) { fln += fn; nc++; }
            }
        }
        if (lane == 0) { wredP[wid] = flp; wredN[wid] = fln; wpc[wid] = pc; wnc[wid] = nc; }
        __syncthreads();
        if (tid == 0) {
            float sp = 0.f, sn = 0.f; int cp = 0, cn = 0;
#pragma unroll
            for (int w = 0; w < 8; ++w) { sp += wredP[w]; sn += wredN[w]; cp += wpc[w]; cn += wnc[w]; }
            atomicAdd(&g_acc[0], (double)sp);
            atomicAdd(&g_acc[1], (double)sn);
            if (cp) atomicAdd(&g_cnt[0], (unsigned)cp);
            if (cn) atomicAdd(&g_cnt[1], (unsigned)cn);
        }
    }
}

// ---------------- normalize + distil: comb -> g_re (tf32-rounded) ----------------
__device__ __forceinline__ float blockReduce128(float v, volatile float* red) {
#pragma unroll
    for (int o = 16; o > 0; o >>= 1) v += __shfl_down_sync(0xffffffffu, v, o);
    __syncthreads();
    if ((threadIdx.x & 31) == 0) red[threadIdx.x >> 5] = v;
    __syncthreads();
    return red[0] + red[1] + red[2] + red[3];
}

__global__ void __launch_bounds__(128)
normalize_kernel(const float* __restrict__ traj,
                 const int* __restrict__ sids,
                 const int* __restrict__ oids)
{
    const int r   = blockIdx.x;
    const int tid = threadIdx.x;
    __shared__ float sp[512];
    __shared__ float comb[512];
    __shared__ float red[4];

    const int b = r / PPB;
    const int p = r - b * PPB;

    float ssp = 0.f, sre = 0.f;
    for (int k = tid; k < 512; k += 128) {
        float a = g_sp[(size_t)r * 512 + k];
        float e = g_re[(size_t)r * 512 + k];
        sp[k] = a; comb[k] = e;
        ssp += a * a; sre += e * e;
    }
    float tssp = blockReduce128(ssp, red);
    float tsre = blockReduce128(sre, red);
    float inv_sp = 1.f / fmaxf(sqrtf(tssp), 1e-12f);
    float inv_re = 1.f / fmaxf(sqrtf(tsre), 1e-12f);

    float ssc = 0.f;
    for (int k = tid; k < 512; k += 128) {
        float c = sp[k] * inv_sp + comb[k] * inv_re;
        comb[k] = c;
        ssc += c * c;
    }
    float tssc = blockReduce128(ssc, red);
    float inv_c = 1.f / fmaxf(sqrtf(tssc), 1e-12f);
    for (int k = tid; k < 512; k += 128)
        g_re[(size_t)r * 512 + k] = to_tf32(comb[k] * inv_c);

    const float* ts = traj + ((size_t)b * NDET + sids[p]) * 256;
    const float* to = traj + ((size_t)b * NDET + oids[p]) * 256;
    float d = 0.f;
    for (int k = tid; k < 256; k += 128) d += fabsf(ts[k] - sp[k]);
    for (int k = tid; k < 256; k += 128) d += fabsf(to[k] - sp[256 + k]);
    float td = blockReduce128(d, red);
    if (tid == 0) atomicAdd(&g_acc[2], (double)td);
}

// ---------------- finalize ----------------
__global__ void finalize_kernel(float* __restrict__ out) {
    double pc = (double)(g_cnt[0] > 0u ? g_cnt[0] : 1u);
    double nc = (double)(g_cnt[1] > 0u ? g_cnt[1] : 1u);
    double total = g_acc[0] / (pc * (double)NB)
                 + g_acc[1] / (nc * (double)NB)
                 + g_acc[2] / ((double)MROWS * 512.0);
    out[0] = (float)total;
}

// ---------------- launch ----------------
extern "C" void kernel_launch(void* const* d_in, const int* in_sizes, int n_in,
                              void* d_out, int out_size)
{
    const float* det    = (const float*)d_in[0];
    const float* traj   = (const float*)d_in[1];
    const float* rp     = (const float*)d_in[2];
    const float* cw     = (const float*)d_in[3];
    const float* W1     = (const float*)d_in[4];
    const float* b1     = (const float*)d_in[5];
    const float* W2     = (const float*)d_in[6];
    const float* b2     = (const float*)d_in[7];
    const float* W3     = (const float*)d_in[8];
    const float* R1     = (const float*)d_in[9];
    const float* rb1    = (const float*)d_in[10];
    const float* R2     = (const float*)d_in[11];
    const float* temp   = (const float*)d_in[12];
    const int*   labels = (const int*)d_in[13];
    const int*   sids   = (const int*)d_in[14];
    const int*   oids   = (const int*)d_in[15];
    float* out = (float*)d_out;

    void *p_det, *p_uv, *p_h2, *p_sp, *p_re, *p_w1u, *p_w1v, *p_w2t, *p_w3t, *p_r2t, *p_cwp;
    cudaGetSymbolAddress(&p_det, g_det);
    cudaGetSymbolAddress(&p_uv, g_UV);
    cudaGetSymbolAddress(&p_h2, g_h2);
    cudaGetSymbolAddress(&p_sp, g_sp);
    cudaGetSymbolAddress(&p_re, g_re);
    cudaGetSymbolAddress(&p_w1u, g_W1tU);
    cudaGetSymbolAddress(&p_w1v, g_W1tV);
    cudaGetSymbolAddress(&p_w2t, g_W2t);
    cudaGetSymbolAddress(&p_w3t, g_W3t);
    cudaGetSymbolAddress(&p_r2t, g_R2t);
    cudaGetSymbolAddress(&p_cwp, g_cwp);
    float* DET = (float*)p_det;
    float* UV  = (float*)p_uv;
    float* H2  = (float*)p_h2;
    float* SP  = (float*)p_sp;
    float* RE  = (float*)p_re;
    float* W1U = (float*)p_w1u;
    float* W1V = (float*)p_w1v;
    float* W2T = (float*)p_w2t;
    float* W3T = (float*)p_w3t;
    float* R2T = (float*)p_r2t;
    float* CWP = (float*)p_cwp;

    cudaFuncSetAttribute(mma_gemm<0>, cudaFuncAttributeMaxDynamicSharedMemorySize, GEMM_SMEM);
    cudaFuncSetAttribute(mma_gemm<1>, cudaFuncAttributeMaxDynamicSharedMemorySize, GEMM_SMEM);
    cudaFuncSetAttribute(mma_gemm<2>, cudaFuncAttributeMaxDynamicSharedMemorySize, GEMM_SMEM);
    cudaFuncSetAttribute(mma_gemm<3>, cudaFuncAttributeMaxDynamicSharedMemorySize, GEMM_SMEM);

    init_acc_kernel<<<1, 1>>>();

    // prep: round det, transpose + round weights, pad classifier
    round_kernel<<<(768 * 2048) / 256, 256>>>(det, DET, 768 * 2048);
    transpose_kernel<<<dim3(1024 / 32, 2048 / 32), dim3(32, 8)>>>(W1,                       W1U, 2048, 1024);
    transpose_kernel<<<dim3(1024 / 32, 2048 / 32), dim3(32, 8)>>>(W1 + (size_t)2048 * 1024, W1V, 2048, 1024);
    transpose_kernel<<<dim3(1024 / 32, 1024 / 32), dim3(32, 8)>>>(W2, W2T, 1024, 1024);
    transpose_kernel<<<dim3(512  / 32, 1024 / 32), dim3(32, 8)>>>(W3, W3T, 1024, 512);
    transpose_kernel<<<dim3(512  / 32, 256  / 32), dim3(32, 8)>>>(R2, R2T, 256,  512);
    pad_cw_kernel<<<256, 256>>>(cw);

    // U = det @ W1[:2048], V = det @ W1[2048:]
    mma_gemm<0><<<dim3(8, 6), 256, GEMM_SMEM>>>(2048, DET, 2048, W1U, UV,        2048,
                                                nullptr, nullptr, nullptr, nullptr, nullptr, nullptr);
    mma_gemm<0><<<dim3(8, 6), 256, GEMM_SMEM>>>(2048, DET, 2048, W1V, UV + 1024, 2048,
                                                nullptr, nullptr, nullptr, nullptr, nullptr, nullptr);
    // h2 = relu(relu(U_s + V_o + b1) @ W2 + b2)
    mma_gemm<1><<<dim3(8, MROWS / 128), 256, GEMM_SMEM>>>(1024, nullptr, 0, W2T, H2, 1024,
                                                          b1, b2, sids, oids, nullptr, nullptr);
    // so_proj = h2 @ W3
    mma_gemm<0><<<dim3(4, MROWS / 128), 256, GEMM_SMEM>>>(1024, H2, 1024, W3T, SP, 512,
                                                          nullptr, nullptr, nullptr, nullptr, nullptr, nullptr);
    // re = relu(rp @ R1 + rb1) @ R2
    mma_gemm<2><<<dim3(4, MROWS / 128), 256, GEMM_SMEM>>>(256, rp, 12, R2T, RE, 512,
                                                          R1, rb1, nullptr, nullptr, nullptr, nullptr);
    // normalize + distil; comb -> g_re (rounded)
    normalize_kernel<<<MROWS, 128>>>(traj, sids, oids);
    // logits GEMM + fused focal reduction
    mma_gemm<3><<<dim3(1, MROWS / 128), 256, GEMM_SMEM>>>(512, RE, 512, CWP, nullptr, 0,
                                                          nullptr, nullptr, nullptr, nullptr, labels, temp);
    finalize_kernel<<<1, 1>>>(out);
}

// round 6
// speedup vs baseline: 9.0903x; 1.5638x over previous
#include <cuda_runtime.h>
#include <cuda_fp16.h>
#include <math.h>
#include <cstdint>

// ---------------- problem constants ----------------
#define PPB   2256
#define MROWS 36096
#define NDET  48
#define NB    92
#define NLAB  133

// ---------------- scratch ----------------
__device__ __half g_deth[768 * 2048];                 // fp16 det_feats
__device__ float  g_UV[768 * 2048];                   // U | V  (fp32)
__device__ __half g_h2h[(size_t)MROWS * 1024];        // h2 (fp16)
__device__ float  g_sp[(size_t)MROWS * 512];          // so_proj (fp32)
__device__ float  g_re[(size_t)MROWS * 512];          // re raw (fp32)
__device__ __half g_combh[(size_t)MROWS * 512];       // normalized comb (fp16)
__device__ __half g_W1tU[1024 * 2048];
__device__ __half g_W1tV[1024 * 2048];
__device__ __half g_W2t[1024 * 1024];
__device__ __half g_W3t[512 * 1024];
__device__ __half g_R2t[512 * 256];
__device__ __half g_cwp[128 * 512];
__device__ double g_acc[3];
__device__ unsigned int g_cnt[2];

// ---------------- helpers ----------------
__device__ __forceinline__ uint32_t smem_to_u32(const void* p) {
    uint32_t a;
    asm("{ .reg .u64 t; cvta.to.shared.u64 t, %1; cvt.u32.u64 %0, t; }" : "=r"(a) : "l"(p));
    return a;
}
__device__ __forceinline__ uint32_t f2h2(float lo, float hi) {
    __half2 h = __floats2half2_rn(lo, hi);
    return *reinterpret_cast<uint32_t*>(&h);
}
__device__ __forceinline__ void mma16816(float* d,
                                         uint32_t a0, uint32_t a1, uint32_t a2, uint32_t a3,
                                         uint32_t b0, uint32_t b1) {
    asm volatile(
        "mma.sync.aligned.m16n8k16.row.col.f32.f16.f16.f32 "
        "{%0,%1,%2,%3}, {%4,%5,%6,%7}, {%8,%9}, {%0,%1,%2,%3};"
        : "+f"(d[0]), "+f"(d[1]), "+f"(d[2]), "+f"(d[3])
        : "r"(a0), "r"(a1), "r"(a2), "r"(a3), "r"(b0), "r"(b1));
}
__device__ __forceinline__ void ldsm_x4(uint32_t* r, uint32_t saddr) {
    asm volatile("ldmatrix.sync.aligned.m8n8.x4.shared.b16 {%0,%1,%2,%3}, [%4];"
                 : "=r"(r[0]), "=r"(r[1]), "=r"(r[2]), "=r"(r[3]) : "r"(saddr));
}
__device__ __forceinline__ void cp_async16(uint32_t saddr, const void* gaddr) {
    asm volatile("cp.async.cg.shared.global [%0], [%1], 16;" :: "r"(saddr), "l"(gaddr) : "memory");
}
#define CP_COMMIT()  asm volatile("cp.async.commit_group;" ::: "memory")
#define CP_WAIT1()   asm volatile("cp.async.wait_group 1;" ::: "memory")

// ---------------- init / prep ----------------
__global__ void init_acc_kernel() {
    g_acc[0] = 0.0; g_acc[1] = 0.0; g_acc[2] = 0.0;
    g_cnt[0] = 0u;  g_cnt[1] = 0u;
}
__global__ void __launch_bounds__(256)
round_kernel(const float* __restrict__ src, __half* __restrict__ dst, int n) {
    int i = blockIdx.x * 256 + threadIdx.x;
    if (i < n) dst[i] = __float2half_rn(src[i]);
}
__global__ void __launch_bounds__(256)
transpose_kernel(const float* __restrict__ src, __half* __restrict__ dst, int K, int N)
{
    __shared__ float t[32][33];
    int kb = blockIdx.y * 32, nb = blockIdx.x * 32;
    int x = threadIdx.x, y = threadIdx.y;
#pragma unroll
    for (int i = y; i < 32; i += 8) t[i][x] = src[(size_t)(kb + i) * N + nb + x];
    __syncthreads();
#pragma unroll
    for (int i = y; i < 32; i += 8)
        dst[(size_t)(nb + i) * K + kb + x] = __float2half_rn(t[x][i]);
}
__global__ void __launch_bounds__(256)
pad_cw_kernel(const float* __restrict__ cw)
{
    int i = blockIdx.x * 256 + threadIdx.x;
    int n = i >> 9, k = i & 511;
    g_cwp[i] = (n < NB) ? __float2half_rn(cw[(size_t)n * 512 + k]) : __float2half_rn(0.f);
}

__device__ __forceinline__ float focal_loss(float x, float t) {
    float p  = 1.0f / (1.0f + expf(-x));
    float ce = fmaxf(x, 0.0f) - x * t + log1pf(expf(-fabsf(x)));
    float pt = p * t + (1.0f - p) * (1.0f - t);
    float om = 1.0f - pt;
    float at = 0.25f * t + 0.75f * (1.0f - t);
    return at * ce * om * om;
}

// =====================================================================
// fp16 mma.sync m16n8k16 GEMM, K-chunk 64, 3-stage cp.async pipeline.
// MODE 0: A = half gmem via cp.async, C = fp32.
// MODE 1: A = half(relu(U[urow]+V[vrow]+b1)) from fp32 g_UV; C = half relu(+b2).
// MODE 2: A = half(relu(rp @ R1 + rb1)); C = fp32. (A=rp fp32, b1=R1, b2=rb1)
// MODE 3: A = half gmem; epilogue = fused focal reduction.
// =====================================================================
#define TROWB 144                         // 64 halfs (128B) + 16B pad
#define TILE_BYTES (128 * TROWB)          // 18432
#define NSTAGE 3
#define GEMM_SMEM (2 * NSTAGE * TILE_BYTES)   // 110592

template<int MODE>
__global__ void __launch_bounds__(256, 1)
mma_gemm(int K,
         const void* __restrict__ Ain, int lda,
         const __half* __restrict__ Bt,
         void* __restrict__ Cout, int ldc,
         const float* __restrict__ b1, const float* __restrict__ b2,
         const int* __restrict__ sids, const int* __restrict__ oids,
         const int* __restrict__ labels, const float* __restrict__ temp)
{
    extern __shared__ char smem[];
    __shared__ int urow[128], vrow[128];
    __shared__ float rps[128 * 12];
    __shared__ float wredP[8], wredN[8];
    __shared__ int   wpc[8], wnc[8];

    const int tid  = threadIdx.x;
    const int wid  = tid >> 5;
    const int lane = tid & 31;
    const int rowBlk = blockIdx.y * 128;
    const int colBlk = blockIdx.x * 128;

    const int wm = (wid & 1) * 64;
    const int wn = (wid >> 1) * 32;
    const int g  = lane >> 2;
    const int tg = lane & 3;

    const uint32_t sb  = smem_to_u32(smem);
    const uint32_t sbA = sb;
    const uint32_t sbB = sb + NSTAGE * TILE_BYTES;

    const __half* Ah = (const __half*)Ain;        // MODE 0/3
    const float*  Af = (const float*)Ain;         // MODE 2 (rp)
    float*  Cf = (float*)Cout;
    __half* Ch = (__half*)Cout;

    if (MODE == 1) {
        if (tid < 128) {
            int r = rowBlk + tid;
            int b = r / PPB, p = r - b * PPB;
            urow[tid] = b * NDET + sids[p];
            vrow[tid] = b * NDET + oids[p];
        }
        __syncthreads();
    }
    if (MODE == 2) {
        for (int idx = tid; idx < 128 * 12; idx += 256)
            rps[idx] = Af[(size_t)rowBlk * 12 + idx];
        __syncthreads();
    }

    float acc[4][4][4];
#pragma unroll
    for (int i = 0; i < 4; i++)
#pragma unroll
        for (int j = 0; j < 4; j++)
#pragma unroll
            for (int q = 0; q < 4; q++) acc[i][j][q] = 0.f;

    int amr[4], aq[4];
#pragma unroll
    for (int j = 0; j < 4; ++j) {
        int idx = tid + j * 256;      // 1024 segments = 128 rows x 8 x 16B
        amr[j] = idx >> 3;
        aq[j]  = idx & 7;
    }

    float4 ra[4][2], rav[4][2];   // A staging (MODE 1/2): 8 floats per segment

    auto loadA = [&](int c) {
        const int k0 = c * 64;
#pragma unroll
        for (int j = 0; j < 4; ++j) {
            const int m = amr[j], base = k0 + aq[j] * 8;
            if (MODE == 1) {
                ra[j][0]  = *reinterpret_cast<const float4*>(&g_UV[(size_t)urow[m] * 2048 + base]);
                ra[j][1]  = *reinterpret_cast<const float4*>(&g_UV[(size_t)urow[m] * 2048 + base + 4]);
                rav[j][0] = *reinterpret_cast<const float4*>(&g_UV[(size_t)vrow[m] * 2048 + 1024 + base]);
                rav[j][1] = *reinterpret_cast<const float4*>(&g_UV[(size_t)vrow[m] * 2048 + 1024 + base + 4]);
            } else if (MODE == 2) {
                float4 a0 = *reinterpret_cast<const float4*>(b2 + base);       // rb1
                float4 a1 = *reinterpret_cast<const float4*>(b2 + base + 4);
#pragma unroll
                for (int t = 0; t < 12; ++t) {
                    const float xv = rps[m * 12 + t];
                    const float4 w0 = *reinterpret_cast<const float4*>(b1 + t * 256 + base);      // R1
                    const float4 w1 = *reinterpret_cast<const float4*>(b1 + t * 256 + base + 4);
                    a0.x = fmaf(xv, w0.x, a0.x); a0.y = fmaf(xv, w0.y, a0.y);
                    a0.z = fmaf(xv, w0.z, a0.z); a0.w = fmaf(xv, w0.w, a0.w);
                    a1.x = fmaf(xv, w1.x, a1.x); a1.y = fmaf(xv, w1.y, a1.y);
                    a1.z = fmaf(xv, w1.z, a1.z); a1.w = fmaf(xv, w1.w, a1.w);
                }
                a0.x = fmaxf(a0.x, 0.f); a0.y = fmaxf(a0.y, 0.f);
                a0.z = fmaxf(a0.z, 0.f); a0.w = fmaxf(a0.w, 0.f);
                a1.x = fmaxf(a1.x, 0.f); a1.y = fmaxf(a1.y, 0.f);
                a1.z = fmaxf(a1.z, 0.f); a1.w = fmaxf(a1.w, 0.f);
                ra[j][0] = a0; ra[j][1] = a1;
            }
        }
    };
    auto storeA = [&](int c, int s) {
        const int k0 = c * 64;
#pragma unroll
        for (int j = 0; j < 4; ++j) {
            const int m = amr[j], q = aq[j];
            float4 a0 = ra[j][0], a1 = ra[j][1];
            if (MODE == 1) {
                const int base = k0 + q * 8;
                const float4 v0 = rav[j][0], v1 = rav[j][1];
                const float4 c0 = *reinterpret_cast<const float4*>(b1 + base);
                const float4 c1 = *reinterpret_cast<const float4*>(b1 + base + 4);
                a0.x = fmaxf(a0.x + v0.x + c0.x, 0.f);
                a0.y = fmaxf(a0.y + v0.y + c0.y, 0.f);
                a0.z = fmaxf(a0.z + v0.z + c0.z, 0.f);
                a0.w = fmaxf(a0.w + v0.w + c0.w, 0.f);
                a1.x = fmaxf(a1.x + v1.x + c1.x, 0.f);
                a1.y = fmaxf(a1.y + v1.y + c1.y, 0.f);
                a1.z = fmaxf(a1.z + v1.z + c1.z, 0.f);
                a1.w = fmaxf(a1.w + v1.w + c1.w, 0.f);
            }
            uint4 h;
            h.x = f2h2(a0.x, a0.y); h.y = f2h2(a0.z, a0.w);
            h.z = f2h2(a1.x, a1.y); h.w = f2h2(a1.z, a1.w);
            *reinterpret_cast<uint4*>(smem + s * TILE_BYTES + m * TROWB + q * 16) = h;
        }
    };
    auto issueLoads = [&](int c, int s) {
        const int k0 = c * 64;
#pragma unroll
        for (int j = 0; j < 4; ++j) {
            const int m = amr[j], q = aq[j];
            cp_async16(sbB + (uint32_t)s * TILE_BYTES + (uint32_t)m * TROWB + (uint32_t)q * 16,
                       Bt + (size_t)(colBlk + m) * K + k0 + q * 8);
            if (MODE == 0 || MODE == 3)
                cp_async16(sbA + (uint32_t)s * TILE_BYTES + (uint32_t)m * TROWB + (uint32_t)q * 16,
                           Ah + (size_t)(rowBlk + m) * lda + k0 + q * 8);
        }
    };

    // per-lane ldmatrix addressing
    const int laneRow  = lane & 15;
    const int laneColB = (lane >> 4) * 16;
    const uint32_t aFragBase = sbA + (uint32_t)(wm + laneRow) * TROWB + laneColB;
    const uint32_t bFragBase = sbB + (uint32_t)(wn + laneRow) * TROWB + laneColB;

    auto compute = [&](int s) {
        const uint32_t aB = aFragBase + (uint32_t)s * TILE_BYTES;
        const uint32_t bB = bFragBase + (uint32_t)s * TILE_BYTES;
#pragma unroll
        for (int ks = 0; ks < 4; ++ks) {          // 4 x k16 = 64
            const uint32_t ko = (uint32_t)ks * 32; // 16 halfs
            uint32_t a[4][4], bb[2][4];
#pragma unroll
            for (int mt = 0; mt < 4; ++mt) ldsm_x4(a[mt], aB + (uint32_t)mt * 2304 + ko);
#pragma unroll
            for (int n2 = 0; n2 < 2; ++n2)  ldsm_x4(bb[n2], bB + (uint32_t)n2 * 2304 + ko);
#pragma unroll
            for (int mt = 0; mt < 4; ++mt)
#pragma unroll
                for (int nt = 0; nt < 4; ++nt)
                    mma16816(acc[mt][nt], a[mt][0], a[mt][1], a[mt][2], a[mt][3],
                             bb[nt >> 1][nt & 1], bb[nt >> 1][2 + (nt & 1)]);
        }
    };

    const int nch = K >> 6;   // K-chunk 64; all K multiples of 256

    if (MODE == 1 || MODE == 2) loadA(0);
    issueLoads(0, 0); CP_COMMIT();
    if (MODE == 1 || MODE == 2) { storeA(0, 0); loadA(1); }
    issueLoads(1, 1); CP_COMMIT();
    CP_WAIT1();
    __syncthreads();

    for (int c = 0; c < nch; ++c) {
        const int s = c % 3;
        if (MODE == 1 || MODE == 2) {
            if (c + 1 < nch) storeA(c + 1, (c + 1) % 3);
            if (c + 2 < nch) { loadA(c + 2); issueLoads(c + 2, (c + 2) % 3); }
        } else {
            if (c + 2 < nch) issueLoads(c + 2, (c + 2) % 3);
        }
        CP_COMMIT();
        compute(s);
        CP_WAIT1();
        __syncthreads();
    }

    if (MODE == 0 || MODE == 2) {
        // fp32 outputs
#pragma unroll
        for (int mt = 0; mt < 4; ++mt) {
#pragma unroll
            for (int nt = 0; nt < 4; ++nt) {
                const int col = colBlk + wn + nt * 8 + 2 * tg;
                const int row0 = rowBlk + wm + mt * 16 + g;
                *reinterpret_cast<float2*>(Cf + (size_t)row0 * ldc + col) =
                    make_float2(acc[mt][nt][0], acc[mt][nt][1]);
                *reinterpret_cast<float2*>(Cf + (size_t)(row0 + 8) * ldc + col) =
                    make_float2(acc[mt][nt][2], acc[mt][nt][3]);
            }
        }
    } else if (MODE == 1) {
        // half output with relu(+b2)
#pragma unroll
        for (int mt = 0; mt < 4; ++mt) {
#pragma unroll
            for (int nt = 0; nt < 4; ++nt) {
                const int col = colBlk + wn + nt * 8 + 2 * tg;
                const float2 bb = *reinterpret_cast<const float2*>(b2 + col);
                const int row0 = rowBlk + wm + mt * 16 + g;
                uint32_t h0 = f2h2(fmaxf(acc[mt][nt][0] + bb.x, 0.f),
                                   fmaxf(acc[mt][nt][1] + bb.y, 0.f));
                uint32_t h1 = f2h2(fmaxf(acc[mt][nt][2] + bb.x, 0.f),
                                   fmaxf(acc[mt][nt][3] + bb.y, 0.f));
                *reinterpret_cast<uint32_t*>(Ch + (size_t)row0 * ldc + col)       = h0;
                *reinterpret_cast<uint32_t*>(Ch + (size_t)(row0 + 8) * ldc + col) = h1;
            }
        }
    } else {
        // ---- MODE 3: stage logits in smem, fused focal reduction ----
        float* stageL = reinterpret_cast<float*>(smem);    // [128][132]
#pragma unroll
        for (int mt = 0; mt < 4; ++mt) {
#pragma unroll
            for (int nt = 0; nt < 4; ++nt) {
                const int col = wn + nt * 8 + 2 * tg;
                const int r0  = wm + mt * 16 + g;
                *reinterpret_cast<float2*>(&stageL[r0 * 132 + col]) =
                    make_float2(acc[mt][nt][0], acc[mt][nt][1]);
                *reinterpret_cast<float2*>(&stageL[(r0 + 8) * 132 + col]) =
                    make_float2(acc[mt][nt][2], acc[mt][nt][3]);
            }
        }
        __syncthreads();

        const float inv_t = 1.0f / temp[0];
        float flp = 0.f, fln = 0.f;
        int pc = 0, nc = 0;
#pragma unroll 1
        for (int i = 0; i < 16; ++i) {
            const int r = wid * 16 + i;
            const int* lab = labels + (size_t)(rowBlk + r) * NLAB;
            const int l0 = lab[0];
            float fp = 0.f, fn = 0.f;
            bool any = false;
            for (int c = lane; c < NB; c += 32) {
                const int t = lab[1 + c];
                const float x = stageL[r * 132 + c] * inv_t;
                fp += focal_loss(x, (float)t);
                fn += focal_loss(x, 0.f);
                any |= (t > 0);
            }
#pragma unroll
            for (int o = 16; o > 0; o >>= 1) {
                fp += __shfl_xor_sync(0xffffffffu, fp, o);
                fn += __shfl_xor_sync(0xffffffffu, fn, o);
            }
            const bool pos = __any_sync(0xffffffffu, any);
            const bool neg = (l0 > 0);
            if (lane == 0) {
                if (pos) { flp += fp; pc++; }
                if (neg) { fln += fn; nc++; }
            }
        }
        if (lane == 0) { wredP[wid] = flp; wredN[wid] = fln; wpc[wid] = pc; wnc[wid] = nc; }
        __syncthreads();
        if (tid == 0) {
            float sp = 0.f, sn = 0.f; int cp = 0, cn = 0;
#pragma unroll
            for (int w = 0; w < 8; ++w) { sp += wredP[w]; sn += wredN[w]; cp += wpc[w]; cn += wnc[w]; }
            atomicAdd(&g_acc[0], (double)sp);
            atomicAdd(&g_acc[1], (double)sn);
            if (cp) atomicAdd(&g_cnt[0], (unsigned)cp);
            if (cn) atomicAdd(&g_cnt[1], (unsigned)cn);
        }
    }
}

// ---------------- normalize + distil: comb -> g_combh (fp16) ----------------
__device__ __forceinline__ float blockReduce128(float v, volatile float* red) {
#pragma unroll
    for (int o = 16; o > 0; o >>= 1) v += __shfl_down_sync(0xffffffffu, v, o);
    __syncthreads();
    if ((threadIdx.x & 31) == 0) red[threadIdx.x >> 5] = v;
    __syncthreads();
    return red[0] + red[1] + red[2] + red[3];
}

__global__ void __launch_bounds__(128)
normalize_kernel(const float* __restrict__ traj,
                 const int* __restrict__ sids,
                 const int* __restrict__ oids)
{
    const int r   = blockIdx.x;
    const int tid = threadIdx.x;
    __shared__ float sp[512];
    __shared__ float comb[512];
    __shared__ float red[4];

    const int b = r / PPB;
    const int p = r - b * PPB;

    float ssp = 0.f, sre = 0.f;
    for (int k = tid; k < 512; k += 128) {
        float a = g_sp[(size_t)r * 512 + k];
        float e = g_re[(size_t)r * 512 + k];
        sp[k] = a; comb[k] = e;
        ssp += a * a; sre += e * e;
    }
    float tssp = blockReduce128(ssp, red);
    float tsre = blockReduce128(sre, red);
    float inv_sp = 1.f / fmaxf(sqrtf(tssp), 1e-12f);
    float inv_re = 1.f / fmaxf(sqrtf(tsre), 1e-12f);

    float ssc = 0.f;
    for (int k = tid; k < 512; k += 128) {
        float c = sp[k] * inv_sp + comb[k] * inv_re;
        comb[k] = c;
        ssc += c * c;
    }
    float tssc = blockReduce128(ssc, red);
    float inv_c = 1.f / fmaxf(sqrtf(tssc), 1e-12f);
    for (int k = tid; k < 512; k += 128)
        g_combh[(size_t)r * 512 + k] = __float2half_rn(comb[k] * inv_c);

    const float* ts = traj + ((size_t)b * NDET + sids[p]) * 256;
    const float* to = traj + ((size_t)b * NDET + oids[p]) * 256;
    float d = 0.f;
    for (int k = tid; k < 256; k += 128) d += fabsf(ts[k] - sp[k]);
    for (int k = tid; k < 256; k += 128) d += fabsf(to[k] - sp[256 + k]);
    float td = blockReduce128(d, red);
    if (tid == 0) atomicAdd(&g_acc[2], (double)td);
}

// ---------------- finalize ----------------
__global__ void finalize_kernel(float* __restrict__ out) {
    double pc = (double)(g_cnt[0] > 0u ? g_cnt[0] : 1u);
    double nc = (double)(g_cnt[1] > 0u ? g_cnt[1] : 1u);
    double total = g_acc[0] / (pc * (double)NB)
                 + g_acc[1] / (nc * (double)NB)
                 + g_acc[2] / ((double)MROWS * 512.0);
    out[0] = (float)total;
}

// ---------------- launch ----------------
extern "C" void kernel_launch(void* const* d_in, const int* in_sizes, int n_in,
                              void* d_out, int out_size)
{
    const float* det    = (const float*)d_in[0];
    const float* traj   = (const float*)d_in[1];
    const float* rp     = (const float*)d_in[2];
    const float* cw     = (const float*)d_in[3];
    const float* W1     = (const float*)d_in[4];
    const float* b1     = (const float*)d_in[5];
    const float* W2     = (const float*)d_in[6];
    const float* b2     = (const float*)d_in[7];
    const float* W3     = (const float*)d_in[8];
    const float* R1     = (const float*)d_in[9];
    const float* rb1    = (const float*)d_in[10];
    const float* R2     = (const float*)d_in[11];
    const float* temp   = (const float*)d_in[12];
    const int*   labels = (const int*)d_in[13];
    const int*   sids   = (const int*)d_in[14];
    const int*   oids   = (const int*)d_in[15];
    float* out = (float*)d_out;

    void *p_deth, *p_uv, *p_h2h, *p_sp, *p_re, *p_combh,
         *p_w1u, *p_w1v, *p_w2t, *p_w3t, *p_r2t, *p_cwp;
    cudaGetSymbolAddress(&p_deth, g_deth);
    cudaGetSymbolAddress(&p_uv, g_UV);
    cudaGetSymbolAddress(&p_h2h, g_h2h);
    cudaGetSymbolAddress(&p_sp, g_sp);
    cudaGetSymbolAddress(&p_re, g_re);
    cudaGetSymbolAddress(&p_combh, g_combh);
    cudaGetSymbolAddress(&p_w1u, g_W1tU);
    cudaGetSymbolAddress(&p_w1v, g_W1tV);
    cudaGetSymbolAddress(&p_w2t, g_W2t);
    cudaGetSymbolAddress(&p_w3t, g_W3t);
    cudaGetSymbolAddress(&p_r2t, g_R2t);
    cudaGetSymbolAddress(&p_cwp, g_cwp);
    __half* DETH  = (__half*)p_deth;
    float*  UV    = (float*)p_uv;
    __half* H2H   = (__half*)p_h2h;
    float*  SP    = (float*)p_sp;
    float*  RE    = (float*)p_re;
    __half* COMBH = (__half*)p_combh;
    __half* W1U   = (__half*)p_w1u;
    __half* W1V   = (__half*)p_w1v;
    __half* W2T   = (__half*)p_w2t;
    __half* W3T   = (__half*)p_w3t;
    __half* R2T   = (__half*)p_r2t;

    cudaFuncSetAttribute(mma_gemm<0>, cudaFuncAttributeMaxDynamicSharedMemorySize, GEMM_SMEM);
    cudaFuncSetAttribute(mma_gemm<1>, cudaFuncAttributeMaxDynamicSharedMemorySize, GEMM_SMEM);
    cudaFuncSetAttribute(mma_gemm<2>, cudaFuncAttributeMaxDynamicSharedMemorySize, GEMM_SMEM);
    cudaFuncSetAttribute(mma_gemm<3>, cudaFuncAttributeMaxDynamicSharedMemorySize, GEMM_SMEM);

    init_acc_kernel<<<1, 1>>>();

    // prep: halve det + weights, pad classifier
    round_kernel<<<(768 * 2048) / 256, 256>>>(det, DETH, 768 * 2048);
    transpose_kernel<<<dim3(1024 / 32, 2048 / 32), dim3(32, 8)>>>(W1,                       W1U, 2048, 1024);
    transpose_kernel<<<dim3(1024 / 32, 2048 / 32), dim3(32, 8)>>>(W1 + (size_t)2048 * 1024, W1V, 2048, 1024);
    transpose_kernel<<<dim3(1024 / 32, 1024 / 32), dim3(32, 8)>>>(W2, W2T, 1024, 1024);
    transpose_kernel<<<dim3(512  / 32, 1024 / 32), dim3(32, 8)>>>(W3, W3T, 1024, 512);
    transpose_kernel<<<dim3(512  / 32, 256  / 32), dim3(32, 8)>>>(R2, R2T, 256,  512);
    pad_cw_kernel<<<256, 256>>>(cw);

    // U = det @ W1[:2048], V = det @ W1[2048:]   (fp32 out)
    mma_gemm<0><<<dim3(8, 6), 256, GEMM_SMEM>>>(2048, DETH, 2048, W1U, UV,        2048,
                                                nullptr, nullptr, nullptr, nullptr, nullptr, nullptr);
    mma_gemm<0><<<dim3(8, 6), 256, GEMM_SMEM>>>(2048, DETH, 2048, W1V, UV + 1024, 2048,
                                                nullptr, nullptr, nullptr, nullptr, nullptr, nullptr);
    // h2 = relu(relu(U_s + V_o + b1) @ W2 + b2)  (fp16 out)
    mma_gemm<1><<<dim3(8, MROWS / 128), 256, GEMM_SMEM>>>(1024, nullptr, 0, W2T, H2H, 1024,
                                                          b1, b2, sids, oids, nullptr, nullptr);
    // so_proj = h2 @ W3   (fp32 out)
    mma_gemm<0><<<dim3(4, MROWS / 128), 256, GEMM_SMEM>>>(1024, H2H, 1024, W3T, SP, 512,
                                                          nullptr, nullptr, nullptr, nullptr, nullptr, nullptr);
    // re = relu(rp @ R1 + rb1) @ R2   (fp32 out)
    mma_gemm<2><<<dim3(4, MROWS / 128), 256, GEMM_SMEM>>>(256, rp, 12, R2T, RE, 512,
                                                          R1, rb1, nullptr, nullptr, nullptr, nullptr);
    // normalize + distil; comb -> g_combh (fp16)
    normalize_kernel<<<MROWS, 128>>>(traj, sids, oids);
    // logits GEMM + fused focal reduction
    mma_gemm<3><<<dim3(1, MROWS / 128), 256, GEMM_SMEM>>>(512, COMBH, 512, (__half*)p_cwp, nullptr, 0,
                                                          nullptr, nullptr, nullptr, nullptr, labels, temp);
    finalize_kernel<<<1, 1>>>(out);
}

// round 7
// speedup vs baseline: 11.1834x; 1.2303x over previous
#include <cuda_runtime.h>
#include <cuda_fp16.h>
#include <math.h>
#include <cstdint>

// ---------------- problem constants ----------------
#define PPB   2256
#define MROWS 36096
#define NDET  48
#define NB    92
#define NLAB  133

// ---------------- scratch ----------------
__device__ __half g_deth[768 * 2048];                 // fp16 det_feats
__device__ __half g_UVh[768 * 2048];                  // U'(=U+b1) | V  (fp16)
__device__ __half g_h2h[(size_t)MROWS * 1024];        // h2 (fp16)
__device__ float  g_sp[(size_t)MROWS * 512];          // so_proj (fp32, distil target precision)
__device__ __half g_reh[(size_t)MROWS * 512];         // re raw (fp16)
__device__ __half g_combh[(size_t)MROWS * 512];       // normalized comb (fp16)
__device__ __half g_W1t[2048 * 2048];                 // [W1U^T ; W1V^T]
__device__ __half g_W2t[1024 * 1024];
__device__ __half g_W3t[512 * 1024];
__device__ __half g_R2t[512 * 256];
__device__ __half g_cwp[128 * 512];
__device__ double g_acc[3];
__device__ unsigned int g_cnt[2];

// ---------------- helpers ----------------
__device__ __forceinline__ uint32_t smem_to_u32(const void* p) {
    uint32_t a;
    asm("{ .reg .u64 t; cvta.to.shared.u64 t, %1; cvt.u32.u64 %0, t; }" : "=r"(a) : "l"(p));
    return a;
}
__device__ __forceinline__ uint32_t f2h2(float lo, float hi) {
    __half2 h = __floats2half2_rn(lo, hi);
    return *reinterpret_cast<uint32_t*>(&h);
}
__device__ __forceinline__ uint32_t hadd_relu2(uint32_t a, uint32_t b) {
    __half2 r = __hmax2(__hadd2(*reinterpret_cast<__half2*>(&a),
                                *reinterpret_cast<__half2*>(&b)),
                        __half2(__float2half_rn(0.f), __float2half_rn(0.f)));
    return *reinterpret_cast<uint32_t*>(&r);
}
__device__ __forceinline__ void mma16816(float* d,
                                         uint32_t a0, uint32_t a1, uint32_t a2, uint32_t a3,
                                         uint32_t b0, uint32_t b1) {
    asm volatile(
        "mma.sync.aligned.m16n8k16.row.col.f32.f16.f16.f32 "
        "{%0,%1,%2,%3}, {%4,%5,%6,%7}, {%8,%9}, {%0,%1,%2,%3};"
        : "+f"(d[0]), "+f"(d[1]), "+f"(d[2]), "+f"(d[3])
        : "r"(a0), "r"(a1), "r"(a2), "r"(a3), "r"(b0), "r"(b1));
}
__device__ __forceinline__ void ldsm_x4(uint32_t* r, uint32_t saddr) {
    asm volatile("ldmatrix.sync.aligned.m8n8.x4.shared.b16 {%0,%1,%2,%3}, [%4];"
                 : "=r"(r[0]), "=r"(r[1]), "=r"(r[2]), "=r"(r[3]) : "r"(saddr));
}
__device__ __forceinline__ void cp_async16(uint32_t saddr, const void* gaddr) {
    asm volatile("cp.async.cg.shared.global [%0], [%1], 16;" :: "r"(saddr), "l"(gaddr) : "memory");
}
#define CP_COMMIT()  asm volatile("cp.async.commit_group;" ::: "memory")
#define CP_WAIT1()   asm volatile("cp.async.wait_group 1;" ::: "memory")

// ---------------- init / prep ----------------
__global__ void init_acc_kernel() {
    g_acc[0] = 0.0; g_acc[1] = 0.0; g_acc[2] = 0.0;
    g_cnt[0] = 0u;  g_cnt[1] = 0u;
}
__global__ void __launch_bounds__(256)
round_kernel(const float* __restrict__ src, __half* __restrict__ dst, int n) {
    int i = blockIdx.x * 256 + threadIdx.x;
    if (i < n) dst[i] = __float2half_rn(src[i]);
}
__global__ void __launch_bounds__(256)
transpose_kernel(const float* __restrict__ src, __half* __restrict__ dst, int K, int N)
{
    __shared__ float t[32][33];
    int kb = blockIdx.y * 32, nb = blockIdx.x * 32;
    int x = threadIdx.x, y = threadIdx.y;
#pragma unroll
    for (int i = y; i < 32; i += 8) t[i][x] = src[(size_t)(kb + i) * N + nb + x];
    __syncthreads();
#pragma unroll
    for (int i = y; i < 32; i += 8)
        dst[(size_t)(nb + i) * K + kb + x] = __float2half_rn(t[x][i]);
}
__global__ void __launch_bounds__(256)
pad_cw_kernel(const float* __restrict__ cw)
{
    int i = blockIdx.x * 256 + threadIdx.x;
    int n = i >> 9, k = i & 511;
    g_cwp[i] = (n < NB) ? __float2half_rn(cw[(size_t)n * 512 + k]) : __float2half_rn(0.f);
}

__device__ __forceinline__ float focal_loss(float x, float t) {
    float p  = 1.0f / (1.0f + expf(-x));
    float ce = fmaxf(x, 0.0f) - x * t + log1pf(expf(-fabsf(x)));
    float pt = p * t + (1.0f - p) * (1.0f - t);
    float om = 1.0f - pt;
    float at = 0.25f * t + 0.75f * (1.0f - t);
    return at * ce * om * om;
}

// =====================================================================
// fp16 mma.sync m16n8k16 GEMM, K-chunk 64, 3-stage cp.async pipeline.
// MODE 0: A = half gmem via cp.async, C = fp32.
// MODE 1: A = relu(U'[urow] + V[vrow]) in half2 from g_UVh; C = half relu(+b2).
// MODE 2: A = half(relu(rp @ R1 + rb1)); C = fp16. (Ain=rp fp32, b1=R1, b2=rb1)
// MODE 3: A = half gmem; epilogue = fused focal reduction.
// MODE 4: A = half gmem; C = fp16, cols < 1024 get +b1 (U' fold).
// =====================================================================
#define TROWB 144                         // 64 halfs (128B) + 16B pad
#define TILE_BYTES (128 * TROWB)          // 18432
#define NSTAGE 3
#define GEMM_SMEM (2 * NSTAGE * TILE_BYTES)   // 110592

template<int MODE>
__global__ void __launch_bounds__(256)
mma_gemm(int K,
         const void* __restrict__ Ain, int lda,
         const __half* __restrict__ Bt,
         void* __restrict__ Cout, int ldc,
         const float* __restrict__ b1, const float* __restrict__ b2,
         const int* __restrict__ sids, const int* __restrict__ oids,
         const int* __restrict__ labels, const float* __restrict__ temp)
{
    extern __shared__ char smem[];
    __shared__ int urow[128], vrow[128];
    __shared__ float rps[128 * 12];
    __shared__ float wredP[8], wredN[8];
    __shared__ int   wpc[8], wnc[8];

    const int tid  = threadIdx.x;
    const int wid  = tid >> 5;
    const int lane = tid & 31;
    const int rowBlk = blockIdx.y * 128;
    const int colBlk = blockIdx.x * 128;

    const int wm = (wid & 1) * 64;
    const int wn = (wid >> 1) * 32;
    const int g  = lane >> 2;
    const int tg = lane & 3;

    const uint32_t sb  = smem_to_u32(smem);
    const uint32_t sbA = sb;
    const uint32_t sbB = sb + NSTAGE * TILE_BYTES;

    const __half* Ah = (const __half*)Ain;
    const float*  Af = (const float*)Ain;         // MODE 2 (rp)
    float*  Cf = (float*)Cout;
    __half* Ch = (__half*)Cout;

    if (MODE == 1) {
        if (tid < 128) {
            int r = rowBlk + tid;
            int b = r / PPB, p = r - b * PPB;
            urow[tid] = b * NDET + sids[p];
            vrow[tid] = b * NDET + oids[p];
        }
        __syncthreads();
    }
    if (MODE == 2) {
        for (int idx = tid; idx < 128 * 12; idx += 256)
            rps[idx] = Af[(size_t)rowBlk * 12 + idx];
        __syncthreads();
    }

    float acc[4][4][4];
#pragma unroll
    for (int i = 0; i < 4; i++)
#pragma unroll
        for (int j = 0; j < 4; j++)
#pragma unroll
            for (int q = 0; q < 4; q++) acc[i][j][q] = 0.f;

    int amr[4], aq[4];
#pragma unroll
    for (int j = 0; j < 4; ++j) {
        int idx = tid + j * 256;      // 1024 segments = 128 rows x 8 x 16B
        amr[j] = idx >> 3;
        aq[j]  = idx & 7;
    }

    uint4 ua[4], va[4];           // MODE 1 staging (half data)
    float4 rf[4][2];              // MODE 2 staging (fp32)

    auto loadA = [&](int c) {
        const int k0 = c * 64;
#pragma unroll
        for (int j = 0; j < 4; ++j) {
            const int m = amr[j], base = k0 + aq[j] * 8;
            if (MODE == 1) {
                ua[j] = *reinterpret_cast<const uint4*>(&g_UVh[(size_t)urow[m] * 2048 + base]);
                va[j] = *reinterpret_cast<const uint4*>(&g_UVh[(size_t)vrow[m] * 2048 + 1024 + base]);
            } else if (MODE == 2) {
                float4 a0 = *reinterpret_cast<const float4*>(b2 + base);       // rb1
                float4 a1 = *reinterpret_cast<const float4*>(b2 + base + 4);
#pragma unroll
                for (int t = 0; t < 12; ++t) {
                    const float xv = rps[m * 12 + t];
                    const float4 w0 = *reinterpret_cast<const float4*>(b1 + t * 256 + base);      // R1
                    const float4 w1 = *reinterpret_cast<const float4*>(b1 + t * 256 + base + 4);
                    a0.x = fmaf(xv, w0.x, a0.x); a0.y = fmaf(xv, w0.y, a0.y);
                    a0.z = fmaf(xv, w0.z, a0.z); a0.w = fmaf(xv, w0.w, a0.w);
                    a1.x = fmaf(xv, w1.x, a1.x); a1.y = fmaf(xv, w1.y, a1.y);
                    a1.z = fmaf(xv, w1.z, a1.z); a1.w = fmaf(xv, w1.w, a1.w);
                }
                a0.x = fmaxf(a0.x, 0.f); a0.y = fmaxf(a0.y, 0.f);
                a0.z = fmaxf(a0.z, 0.f); a0.w = fmaxf(a0.w, 0.f);
                a1.x = fmaxf(a1.x, 0.f); a1.y = fmaxf(a1.y, 0.f);
                a1.z = fmaxf(a1.z, 0.f); a1.w = fmaxf(a1.w, 0.f);
                rf[j][0] = a0; rf[j][1] = a1;
            }
        }
    };
    auto storeA = [&](int s) {
#pragma unroll
        for (int j = 0; j < 4; ++j) {
            const int m = amr[j], q = aq[j];
            uint4 h;
            if (MODE == 1) {
                h.x = hadd_relu2(ua[j].x, va[j].x);
                h.y = hadd_relu2(ua[j].y, va[j].y);
                h.z = hadd_relu2(ua[j].z, va[j].z);
                h.w = hadd_relu2(ua[j].w, va[j].w);
            } else {  // MODE 2
                h.x = f2h2(rf[j][0].x, rf[j][0].y);
                h.y = f2h2(rf[j][0].z, rf[j][0].w);
                h.z = f2h2(rf[j][1].x, rf[j][1].y);
                h.w = f2h2(rf[j][1].z, rf[j][1].w);
            }
            *reinterpret_cast<uint4*>(smem + s * TILE_BYTES + m * TROWB + q * 16) = h;
        }
    };
    auto issueLoads = [&](int c, int s) {
        const int k0 = c * 64;
#pragma unroll
        for (int j = 0; j < 4; ++j) {
            const int m = amr[j], q = aq[j];
            cp_async16(sbB + (uint32_t)s * TILE_BYTES + (uint32_t)m * TROWB + (uint32_t)q * 16,
                       Bt + (size_t)(colBlk + m) * K + k0 + q * 8);
            if (MODE == 0 || MODE == 3 || MODE == 4)
                cp_async16(sbA + (uint32_t)s * TILE_BYTES + (uint32_t)m * TROWB + (uint32_t)q * 16,
                           Ah + (size_t)(rowBlk + m) * lda + k0 + q * 8);
        }
    };

    const int laneRow  = lane & 15;
    const int laneColB = (lane >> 4) * 16;
    const uint32_t aFragBase = sbA + (uint32_t)(wm + laneRow) * TROWB + laneColB;
    const uint32_t bFragBase = sbB + (uint32_t)(wn + laneRow) * TROWB + laneColB;

    auto compute = [&](int s) {
        const uint32_t aB = aFragBase + (uint32_t)s * TILE_BYTES;
        const uint32_t bB = bFragBase + (uint32_t)s * TILE_BYTES;
#pragma unroll
        for (int ks = 0; ks < 4; ++ks) {
            const uint32_t ko = (uint32_t)ks * 32;
            uint32_t a[4][4], bb[2][4];
#pragma unroll
            for (int mt = 0; mt < 4; ++mt) ldsm_x4(a[mt], aB + (uint32_t)mt * 2304 + ko);
#pragma unroll
            for (int n2 = 0; n2 < 2; ++n2)  ldsm_x4(bb[n2], bB + (uint32_t)n2 * 2304 + ko);
#pragma unroll
            for (int mt = 0; mt < 4; ++mt)
#pragma unroll
                for (int nt = 0; nt < 4; ++nt)
                    mma16816(acc[mt][nt], a[mt][0], a[mt][1], a[mt][2], a[mt][3],
                             bb[nt >> 1][nt & 1], bb[nt >> 1][2 + (nt & 1)]);
        }
    };

    const int nch = K >> 6;
    const bool FEED = (MODE == 1 || MODE == 2);

    if (FEED) loadA(0);
    issueLoads(0, 0); CP_COMMIT();
    if (FEED) { storeA(0); loadA(1); }
    issueLoads(1, 1); CP_COMMIT();
    CP_WAIT1();
    __syncthreads();

    for (int c = 0; c < nch; ++c) {
        const int s = c % 3;
        if (FEED) {
            if (c + 1 < nch) storeA((c + 1) % 3);
            if (c + 2 < nch) { loadA(c + 2); issueLoads(c + 2, (c + 2) % 3); }
        } else {
            if (c + 2 < nch) issueLoads(c + 2, (c + 2) % 3);
        }
        CP_COMMIT();
        compute(s);
        CP_WAIT1();
        __syncthreads();
    }

    if (MODE == 0) {
#pragma unroll
        for (int mt = 0; mt < 4; ++mt) {
#pragma unroll
            for (int nt = 0; nt < 4; ++nt) {
                const int col = colBlk + wn + nt * 8 + 2 * tg;
                const int row0 = rowBlk + wm + mt * 16 + g;
                *reinterpret_cast<float2*>(Cf + (size_t)row0 * ldc + col) =
                    make_float2(acc[mt][nt][0], acc[mt][nt][1]);
                *reinterpret_cast<float2*>(Cf + (size_t)(row0 + 8) * ldc + col) =
                    make_float2(acc[mt][nt][2], acc[mt][nt][3]);
            }
        }
    } else if (MODE == 1) {
#pragma unroll
        for (int mt = 0; mt < 4; ++mt) {
#pragma unroll
            for (int nt = 0; nt < 4; ++nt) {
                const int col = colBlk + wn + nt * 8 + 2 * tg;
                const float2 bb = *reinterpret_cast<const float2*>(b2 + col);
                const int row0 = rowBlk + wm + mt * 16 + g;
                uint32_t h0 = f2h2(fmaxf(acc[mt][nt][0] + bb.x, 0.f),
                                   fmaxf(acc[mt][nt][1] + bb.y, 0.f));
                uint32_t h1 = f2h2(fmaxf(acc[mt][nt][2] + bb.x, 0.f),
                                   fmaxf(acc[mt][nt][3] + bb.y, 0.f));
                *reinterpret_cast<uint32_t*>(Ch + (size_t)row0 * ldc + col)       = h0;
                *reinterpret_cast<uint32_t*>(Ch + (size_t)(row0 + 8) * ldc + col) = h1;
            }
        }
    } else if (MODE == 2 || MODE == 4) {
        const bool addb = (MODE == 4) && (colBlk < 1024);
#pragma unroll
        for (int mt = 0; mt < 4; ++mt) {
#pragma unroll
            for (int nt = 0; nt < 4; ++nt) {
                const int col = colBlk + wn + nt * 8 + 2 * tg;
                float bx = 0.f, by = 0.f;
                if (addb) { const float2 bb = *reinterpret_cast<const float2*>(b1 + col); bx = bb.x; by = bb.y; }
                const int row0 = rowBlk + wm + mt * 16 + g;
                uint32_t h0 = f2h2(acc[mt][nt][0] + bx, acc[mt][nt][1] + by);
                uint32_t h1 = f2h2(acc[mt][nt][2] + bx, acc[mt][nt][3] + by);
                *reinterpret_cast<uint32_t*>(Ch + (size_t)row0 * ldc + col)       = h0;
                *reinterpret_cast<uint32_t*>(Ch + (size_t)(row0 + 8) * ldc + col) = h1;
            }
        }
    } else {
        // ---- MODE 3: stage logits in smem, fused focal reduction ----
        float* stageL = reinterpret_cast<float*>(smem);    // [128][132]
#pragma unroll
        for (int mt = 0; mt < 4; ++mt) {
#pragma unroll
            for (int nt = 0; nt < 4; ++nt) {
                const int col = wn + nt * 8 + 2 * tg;
                const int r0  = wm + mt * 16 + g;
                *reinterpret_cast<float2*>(&stageL[r0 * 132 + col]) =
                    make_float2(acc[mt][nt][0], acc[mt][nt][1]);
                *reinterpret_cast<float2*>(&stageL[(r0 + 8) * 132 + col]) =
                    make_float2(acc[mt][nt][2], acc[mt][nt][3]);
            }
        }
        __syncthreads();

        const float inv_t = 1.0f / temp[0];
        float flp = 0.f, fln = 0.f;
        int pc = 0, nc = 0;
#pragma unroll 1
        for (int i = 0; i < 16; ++i) {
            const int r = wid * 16 + i;
            const int* lab = labels + (size_t)(rowBlk + r) * NLAB;
            const int l0 = lab[0];
            float fp = 0.f, fn = 0.f;
            bool any = false;
            for (int c = lane; c < NB; c += 32) {
                const int t = lab[1 + c];
                const float x = stageL[r * 132 + c] * inv_t;
                fp += focal_loss(x, (float)t);
                fn += focal_loss(x, 0.f);
                any |= (t > 0);
            }
#pragma unroll
            for (int o = 16; o > 0; o >>= 1) {
                fp += __shfl_xor_sync(0xffffffffu, fp, o);
                fn += __shfl_xor_sync(0xffffffffu, fn, o);
            }
            const bool pos = __any_sync(0xffffffffu, any);
            const bool neg = (l0 > 0);
            if (lane == 0) {
                if (pos) { flp += fp; pc++; }
                if (neg) { fln += fn; nc++; }
            }
        }
        if (lane == 0) { wredP[wid] = flp; wredN[wid] = fln; wpc[wid] = pc; wnc[wid] = nc; }
        __syncthreads();
        if (tid == 0) {
            float sp = 0.f, sn = 0.f; int cp = 0, cn = 0;
#pragma unroll
            for (int w = 0; w < 8; ++w) { sp += wredP[w]; sn += wredN[w]; cp += wpc[w]; cn += wnc[w]; }
            atomicAdd(&g_acc[0], (double)sp);
            atomicAdd(&g_acc[1], (double)sn);
            if (cp) atomicAdd(&g_cnt[0], (unsigned)cp);
            if (cn) atomicAdd(&g_cnt[1], (unsigned)cn);
        }
    }
}

// ---------------- normalize + distil: warp per row, 4 rows/block ----------------
__global__ void __launch_bounds__(128)
normalize_kernel(const float* __restrict__ traj,
                 const int* __restrict__ sids,
                 const int* __restrict__ oids)
{
    const int tid  = threadIdx.x;
    const int wrp  = tid >> 5;
    const int lane = tid & 31;
    const int r    = blockIdx.x * 4 + wrp;
    __shared__ float dsh[4];

    const int b = r / PPB;
    const int p = r - b * PPB;

    // each lane owns cols [lane*16, lane*16+16)
    float sp[16], re[16];
    {
        const float4* spv = reinterpret_cast<const float4*>(g_sp + (size_t)r * 512) + lane * 4;
        const uint4*  rev = reinterpret_cast<const uint4*>(g_reh + (size_t)r * 512) + lane * 2;
#pragma unroll
        for (int i = 0; i < 4; ++i) {
            float4 v = spv[i];
            sp[i * 4 + 0] = v.x; sp[i * 4 + 1] = v.y; sp[i * 4 + 2] = v.z; sp[i * 4 + 3] = v.w;
        }
#pragma unroll
        for (int i = 0; i < 2; ++i) {
            uint4 u = rev[i];
            const __half2* h = reinterpret_cast<const __half2*>(&u);
#pragma unroll
            for (int j = 0; j < 4; ++j) {
                float2 f = __half22float2(h[j]);
                re[i * 8 + j * 2]     = f.x;
                re[i * 8 + j * 2 + 1] = f.y;
            }
        }
    }
    float ssp = 0.f, sre = 0.f;
#pragma unroll
    for (int i = 0; i < 16; ++i) { ssp += sp[i] * sp[i]; sre += re[i] * re[i]; }
#pragma unroll
    for (int o = 16; o > 0; o >>= 1) {
        ssp += __shfl_xor_sync(0xffffffffu, ssp, o);
        sre += __shfl_xor_sync(0xffffffffu, sre, o);
    }
    const float inv_sp = 1.f / fmaxf(sqrtf(ssp), 1e-12f);
    const float inv_re = 1.f / fmaxf(sqrtf(sre), 1e-12f);

    float comb[16];
    float ssc = 0.f;
#pragma unroll
    for (int i = 0; i < 16; ++i) {
        comb[i] = sp[i] * inv_sp + re[i] * inv_re;
        ssc += comb[i] * comb[i];
    }
#pragma unroll
    for (int o = 16; o > 0; o >>= 1) ssc += __shfl_xor_sync(0xffffffffu, ssc, o);
    const float inv_c = 1.f / fmaxf(sqrtf(ssc), 1e-12f);

    {
        uint4 u[2];
        uint32_t* w = reinterpret_cast<uint32_t*>(u);
#pragma unroll
        for (int j = 0; j < 8; ++j)
            w[j] = f2h2(comb[j * 2] * inv_c, comb[j * 2 + 1] * inv_c);
        uint4* dst = reinterpret_cast<uint4*>(g_combh + (size_t)r * 512) + lane * 2;
        dst[0] = u[0]; dst[1] = u[1];
    }

    // distil: lanes 0..15 -> ts cols 0..255; lanes 16..31 -> to cols 256..511
    const float* tr = (lane < 16)
        ? traj + ((size_t)b * NDET + sids[p]) * 256 + lane * 16
        : traj + ((size_t)b * NDET + oids[p]) * 256 + (lane - 16) * 16;
    float d = 0.f;
#pragma unroll
    for (int i = 0; i < 16; ++i) d += fabsf(tr[i] - sp[i]);
#pragma unroll
    for (int o = 16; o > 0; o >>= 1) d += __shfl_xor_sync(0xffffffffu, d, o);
    if (lane == 0) dsh[wrp] = d;
    __syncthreads();
    if (tid == 0)
        atomicAdd(&g_acc[2], (double)(dsh[0] + dsh[1] + dsh[2] + dsh[3]));
}

// ---------------- finalize ----------------
__global__ void finalize_kernel(float* __restrict__ out) {
    double pc = (double)(g_cnt[0] > 0u ? g_cnt[0] : 1u);
    double nc = (double)(g_cnt[1] > 0u ? g_cnt[1] : 1u);
    double total = g_acc[0] / (pc * (double)NB)
                 + g_acc[1] / (nc * (double)NB)
                 + g_acc[2] / ((double)MROWS * 512.0);
    out[0] = (float)total;
}

// ---------------- launch ----------------
extern "C" void kernel_launch(void* const* d_in, const int* in_sizes, int n_in,
                              void* d_out, int out_size)
{
    const float* det    = (const float*)d_in[0];
    const float* traj   = (const float*)d_in[1];
    const float* rp     = (const float*)d_in[2];
    const float* cw     = (const float*)d_in[3];
    const float* W1     = (const float*)d_in[4];
    const float* b1     = (const float*)d_in[5];
    const float* W2     = (const float*)d_in[6];
    const float* b2     = (const float*)d_in[7];
    const float* W3     = (const float*)d_in[8];
    const float* R1     = (const float*)d_in[9];
    const float* rb1    = (const float*)d_in[10];
    const float* R2     = (const float*)d_in[11];
    const float* temp   = (const float*)d_in[12];
    const int*   labels = (const int*)d_in[13];
    const int*   sids   = (const int*)d_in[14];
    const int*   oids   = (const int*)d_in[15];
    float* out = (float*)d_out;

    void *p_deth, *p_uvh, *p_h2h, *p_sp, *p_reh, *p_combh,
         *p_w1t, *p_w2t, *p_w3t, *p_r2t, *p_cwp;
    cudaGetSymbolAddress(&p_deth, g_deth);
    cudaGetSymbolAddress(&p_uvh, g_UVh);
    cudaGetSymbolAddress(&p_h2h, g_h2h);
    cudaGetSymbolAddress(&p_sp, g_sp);
    cudaGetSymbolAddress(&p_reh, g_reh);
    cudaGetSymbolAddress(&p_combh, g_combh);
    cudaGetSymbolAddress(&p_w1t, g_W1t);
    cudaGetSymbolAddress(&p_w2t, g_W2t);
    cudaGetSymbolAddress(&p_w3t, g_W3t);
    cudaGetSymbolAddress(&p_r2t, g_R2t);
    cudaGetSymbolAddress(&p_cwp, g_cwp);
    __half* DETH  = (__half*)p_deth;
    __half* UVH   = (__half*)p_uvh;
    __half* H2H   = (__half*)p_h2h;
    float*  SP    = (float*)p_sp;
    __half* REH   = (__half*)p_reh;
    __half* COMBH = (__half*)p_combh;
    __half* W1T   = (__half*)p_w1t;
    __half* W2T   = (__half*)p_w2t;
    __half* W3T   = (__half*)p_w3t;
    __half* R2T   = (__half*)p_r2t;

    cudaFuncSetAttribute(mma_gemm<0>, cudaFuncAttributeMaxDynamicSharedMemorySize, GEMM_SMEM);
    cudaFuncSetAttribute(mma_gemm<1>, cudaFuncAttributeMaxDynamicSharedMemorySize, GEMM_SMEM);
    cudaFuncSetAttribute(mma_gemm<2>, cudaFuncAttributeMaxDynamicSharedMemorySize, GEMM_SMEM);
    cudaFuncSetAttribute(mma_gemm<3>, cudaFuncAttributeMaxDynamicSharedMemorySize, GEMM_SMEM);
    cudaFuncSetAttribute(mma_gemm<4>, cudaFuncAttributeMaxDynamicSharedMemorySize, GEMM_SMEM);

    init_acc_kernel<<<1, 1>>>();

    // prep
    round_kernel<<<(768 * 2048) / 256, 256>>>(det, DETH, 768 * 2048);
    // W1T rows 0..1023 = W1U^T; rows 1024..2047 = W1V^T
    transpose_kernel<<<dim3(1024 / 32, 2048 / 32), dim3(32, 8)>>>(W1,                       W1T,                      2048, 1024);
    transpose_kernel<<<dim3(1024 / 32, 2048 / 32), dim3(32, 8)>>>(W1 + (size_t)2048 * 1024, W1T + (size_t)1024 * 2048, 2048, 1024);
    transpose_kernel<<<dim3(1024 / 32, 1024 / 32), dim3(32, 8)>>>(W2, W2T, 1024, 1024);
    transpose_kernel<<<dim3(512  / 32, 1024 / 32), dim3(32, 8)>>>(W3, W3T, 1024, 512);
    transpose_kernel<<<dim3(512  / 32, 256  / 32), dim3(32, 8)>>>(R2, R2T, 256,  512);
    pad_cw_kernel<<<256, 256>>>(cw);

    // UV' = det @ [W1U | W1V]  (fp16 out, +b1 on U half)
    mma_gemm<4><<<dim3(16, 6), 256, GEMM_SMEM>>>(2048, DETH, 2048, W1T, UVH, 2048,
                                                 b1, nullptr, nullptr, nullptr, nullptr, nullptr);
    // h2 = relu(relu(U'_s + V_o) @ W2 + b2)  (fp16 out)
    mma_gemm<1><<<dim3(8, MROWS / 128), 256, GEMM_SMEM>>>(1024, nullptr, 0, W2T, H2H, 1024,
                                                          nullptr, b2, sids, oids, nullptr, nullptr);
    // so_proj = h2 @ W3   (fp32 out)
    mma_gemm<0><<<dim3(4, MROWS / 128), 256, GEMM_SMEM>>>(1024, H2H, 1024, W3T, SP, 512,
                                                          nullptr, nullptr, nullptr, nullptr, nullptr, nullptr);
    // re = relu(rp @ R1 + rb1) @ R2   (fp16 out)
    mma_gemm<2><<<dim3(4, MROWS / 128), 256, GEMM_SMEM>>>(256, rp, 12, R2T, REH, 512,
                                                          R1, rb1, nullptr, nullptr, nullptr, nullptr);
    // normalize + distil; comb -> g_combh (fp16)
    normalize_kernel<<<MROWS / 4, 128>>>(traj, sids, oids);
    // logits GEMM + fused focal reduction
    mma_gemm<3><<<dim3(1, MROWS / 128), 256, GEMM_SMEM>>>(512, COMBH, 512, (__half*)p_cwp, nullptr, 0,
                                                          nullptr, nullptr, nullptr, nullptr, labels, temp);
    finalize_kernel<<<1, 1>>>(out);
}